// round 10
// baseline (speedup 1.0000x reference)
#include <cuda_runtime.h>
#include <cuda_bf16.h>
#include <cuda_fp16.h>
#include <cstdint>

// Problem constants
#define LQ      43054
#define NHEADS  8

// Padded value geometry: each level padded +2 on every side.
#define PADROWS 45822
#define ZPN     (PADROWS * 16)

// Scratch (device globals; no runtime allocation allowed)
__device__ __half g_value_h[PADROWS * 256];     // projected value, fp16, PADDED
__device__ float  g_qout[LQ * 384];             // [0,256)=offsets, [256,384)=logits
__device__ __half g_acch[LQ * 256];             // msda out hi (fp16)
__device__ __half g_accl[LQ * 256];             // msda out lo (fp16 residual)
__device__ __half g_Wv[256 * 256];
__device__ __half g_Wq[384 * 256];              // merged Ws|Wa
__device__ __half g_Wo[256 * 256];
__device__ float g_bq[384];                     // merged bias bs|ba

#define SW128(o) ((o) ^ (((o) >> 3) & 0x70))

__device__ __forceinline__ uint32_t smem_u32(const void* p) {
    uint32_t a;
    asm("{ .reg .u64 t; cvta.to.shared.u64 t, %1; cvt.u32.u64 %0, t; }" : "=r"(a) : "l"(p));
    return a;
}
__device__ __forceinline__ void ldsm4(uint32_t r[4], uint32_t addr) {
    asm volatile("ldmatrix.sync.aligned.m8n8.x4.shared.b16 {%0,%1,%2,%3}, [%4];"
        : "=r"(r[0]), "=r"(r[1]), "=r"(r[2]), "=r"(r[3]) : "r"(addr));
}
__device__ __forceinline__ void mma_f16(float d[4], const uint32_t a[4],
                                        uint32_t b0, uint32_t b1) {
    asm volatile("mma.sync.aligned.m16n8k16.row.col.f32.f16.f16.f32 "
        "{%0,%1,%2,%3}, {%4,%5,%6,%7}, {%8,%9}, {%0,%1,%2,%3};"
        : "+f"(d[0]), "+f"(d[1]), "+f"(d[2]), "+f"(d[3])
        : "r"(a[0]), "r"(a[1]), "r"(a[2]), "r"(a[3]), "r"(b0), "r"(b1));
}
__device__ __forceinline__ uint32_t packh2(float x, float y) {
    __half2 h = __floats2half2_rn(x, y);
    return *(uint32_t*)&h;
}
__device__ __forceinline__ void cpa16(uint32_t d, const void* s) {
    asm volatile("cp.async.cg.shared.global [%0], [%1], 16;" :: "r"(d), "l"(s));
}
#define CP_COMMIT() asm volatile("cp.async.commit_group;" ::: "memory")
template <int Ngrp>
__device__ __forceinline__ void cp_wait() {
    asm volatile("cp.async.wait_group %0;" :: "n"(Ngrp) : "memory");
}

// Map original value row -> padded row index (compile-time divisors).
__device__ __forceinline__ int pad_row(int r) {
    if (r < 32400) { int cy = r / 180, cx = r - cy * 180; return (cy + 2) * 184 + cx + 2; }
    if (r < 40500) { int rr = r - 32400; int cy = rr / 90, cx = rr - cy * 90; return 33856 + (cy + 2) * 94 + cx + 2; }
    if (r < 42525) { int rr = r - 40500; int cy = rr / 45, cx = rr - cy * 45; return 42692 + (cy + 2) * 49 + cx + 2; }
    { int rr = r - 42525; int cy = rr / 23, cx = rr - cy * 23; return 45093 + (cy + 2) * 27 + cx + 2; }
}

// ---------------------------------------------------------------------------
// Combined prep: zero padding borders + fp16 weight transpose + merged bias.
// ---------------------------------------------------------------------------
__global__ __launch_bounds__(256) void prep_all(
    const float* __restrict__ Wv, const float* __restrict__ Ws,
    const float* __restrict__ Wa, const float* __restrict__ Wo,
    const float* __restrict__ bs, const float* __restrict__ ba,
    __half* __restrict__ vp,
    __half* __restrict__ wv, __half* __restrict__ wq, __half* __restrict__ wo,
    float* __restrict__ bq)
{
    int idx = blockIdx.x * 256 + threadIdx.x;
    if (idx < ZPN) {
        int row = idx >> 4, c = idx & 15;
        bool pad;
        if (row < 33856)      { int py = row / 184, px = row - py * 184;
                                pad = (py < 2) | (py >= 182) | (px < 2) | (px >= 182); }
        else if (row < 42692) { int r2 = row - 33856; int py = r2 / 94, px = r2 - py * 94;
                                pad = (py < 2) | (py >= 92) | (px < 2) | (px >= 92); }
        else if (row < 45093) { int r2 = row - 42692; int py = r2 / 49, px = r2 - py * 49;
                                pad = (py < 2) | (py >= 47) | (px < 2) | (px >= 47); }
        else                  { int r2 = row - 45093; int py = r2 / 27, px = r2 - py * 27;
                                pad = (py < 2) | (py >= 25) | (px < 2) | (px >= 25); }
        if (pad) {
            uint4* d = (uint4*)((char*)vp + (size_t)row * 512 + c * 32);
            d[0] = make_uint4(0, 0, 0, 0);
            d[1] = make_uint4(0, 0, 0, 0);
        }
        return;
    }
    idx -= ZPN;
    const float* W;
    __half* dst;
    int N, base, nofs;
    if (idx < 65536)        { W = Wv; dst = wv; N = 256; base = 0;      nofs = 0; }
    else if (idx < 131072)  { W = Ws; dst = wq; N = 256; base = 65536;  nofs = 0; }
    else if (idx < 163840)  { W = Wa; dst = wq; N = 128; base = 131072; nofs = 256; }
    else if (idx < 229376)  { W = Wo; dst = wo; N = 256; base = 163840; nofs = 0; }
    else if (idx < 229376 + 256) { bq[idx - 229376] = bs[idx - 229376]; return; }
    else if (idx < 229376 + 384) { bq[idx - 229376] = ba[idx - 229632]; return; }
    else return;
    int j = idx - base;
    int k = j / N, n = j % N + nofs;
    dst[n * 256 + k] = __float2half_rn(W[j]);
}

// ---------------------------------------------------------------------------
// Tensor-core GEMM, fp16, PASSES=1 or 2 (A split hi/lo), ONE sync per chunk.
//   C[M,N] = A[M,256] @ W[256,N] + bias
// A double-buffered in smem (2 x PASSES*16KB); B via cp.async:
//   PASSES=1: 4 slots up-front (96KB total);
//   PASSES=2: 3-slot ring, B3 issued after chunk-1 sync (112KB total).
// CTA 128x128, 256 thr, 8 warps (4m x 2n), K chunks of 64.
// ---------------------------------------------------------------------------
template <bool ASPLIT, bool OUTHALF, int PASSES>
__global__ __launch_bounds__(256, 2) void gemm_mma(
    const float* __restrict__ A,
    const __half* __restrict__ AhG,
    const __half* __restrict__ AlG,
    const __half* __restrict__ B,
    const float* __restrict__ bias,
    float* __restrict__ C,
    __half* __restrict__ Ch,
    int M, int N)
{
    extern __shared__ char smem[];
    const uint32_t sb = smem_u32(smem);
    constexpr int ABUF = PASSES * 16384;   // one A buffer
    constexpr int BOFF = 2 * ABUF;         // B region start

    const int tid = threadIdx.x;
    const int wid = tid >> 5, lane = tid & 31;
    const int wm = (wid & 3) * 32;
    const int wn = (wid >> 2) * 64;
    const int bm = blockIdx.y * 128;
    const int bn = blockIdx.x * 128;

    float acc[2][8][4];
#pragma unroll
    for (int i = 0; i < 2; i++)
#pragma unroll
        for (int j = 0; j < 8; j++)
#pragma unroll
            for (int k = 0; k < 4; k++) acc[i][j][k] = 0.f;

    const int a_row = lane & 15;
    const int a_k8  = (lane >> 4) << 3;
    const int b_row = (lane & 7) + ((lane & 16) >> 1);
    const int b_k8  = lane & 8;

    const int ld_row = tid >> 1;          // 0..127
    const int ld_kh  = (tid & 1) * 32;    // 0 or 32 (k elements)
    const int grow   = bm + ld_row;
    const bool okA   = grow < M;

    // ---- async B chunk issue into its slot
    auto issueB = [&](int c) {
        const int slot = (PASSES == 1) ? c : (c % 3);
        const int k0 = c * 64;
        const int n = bn + ld_row;
        const __half* s = &B[(size_t)n * 256 + k0 + ld_kh];
        const uint32_t bas = sb + BOFF + slot * 16384;
#pragma unroll
        for (int jj = 0; jj < 4; jj++) {
            uint32_t off = SW128((uint32_t)(ld_row * 128 + (ld_kh + jj * 8) * 2));
            cpa16(bas + off, s + jj * 8);
        }
    };

    // ---- A register staging
    float4 vA[8];           // !ASPLIT
    uint4  sAh[4], sAl[4];  // ASPLIT
    auto stageA = [&](int c) {
        const int k0 = c * 64;
        if (!ASPLIT) {
            const float4* src = (const float4*)&A[(size_t)(okA ? grow : 0) * 256 + k0 + ld_kh];
#pragma unroll
            for (int j = 0; j < 8; j++)
                vA[j] = okA ? src[j] : make_float4(0.f, 0.f, 0.f, 0.f);
        } else {
            const uint4* sh = (const uint4*)&AhG[(size_t)(okA ? grow : 0) * 256 + k0 + ld_kh];
            const uint4* sl = (const uint4*)&AlG[(size_t)(okA ? grow : 0) * 256 + k0 + ld_kh];
#pragma unroll
            for (int j = 0; j < 4; j++) {
                sAh[j] = okA ? sh[j] : make_uint4(0, 0, 0, 0);
                sAl[j] = okA ? sl[j] : make_uint4(0, 0, 0, 0);
            }
        }
    };
    auto commitA = [&](int c) {
        char* aB = smem + (c & 1) * ABUF;
        if (!ASPLIT) {
#pragma unroll
            for (int jj = 0; jj < 4; jj++) {
                float4 v0 = vA[jj * 2 + 0];
                float4 v1 = vA[jj * 2 + 1];
                float vs[8] = {v0.x, v0.y, v0.z, v0.w, v1.x, v1.y, v1.z, v1.w};
                uint4 hi4, lo4;
                uint32_t* hp = (uint32_t*)&hi4;
                uint32_t* lp = (uint32_t*)&lo4;
#pragma unroll
                for (int i = 0; i < 4; i++) {
                    float a0 = vs[2 * i], a1 = vs[2 * i + 1];
                    hp[i] = packh2(a0, a1);
                    if (PASSES == 2) {
                        float h0 = __half2float(__float2half_rn(a0));
                        float h1 = __half2float(__float2half_rn(a1));
                        lp[i] = packh2(a0 - h0, a1 - h1);
                    }
                }
                uint32_t off = SW128((uint32_t)(ld_row * 128 + (ld_kh + jj * 8) * 2));
                *(uint4*)(aB + off) = hi4;
                if (PASSES == 2) *(uint4*)(aB + 16384 + off) = lo4;
            }
        } else {
#pragma unroll
            for (int jj = 0; jj < 4; jj++) {
                uint32_t off = SW128((uint32_t)(ld_row * 128 + (ld_kh + jj * 8) * 2));
                *(uint4*)(aB + off) = sAh[jj];
                if (PASSES == 2) *(uint4*)(aB + 16384 + off) = sAl[jj];
            }
        }
    };

    // ---- MMA over one 64-k chunk
    auto mma_chunk = [&](uint32_t aBase, uint32_t bBase) {
#pragma unroll
        for (int ks = 0; ks < 4; ks++) {
            uint32_t ah[2][4], al[2][4];
#pragma unroll
            for (int mt = 0; mt < 2; mt++) {
                uint32_t aoff = SW128((uint32_t)((wm + mt * 16 + a_row) * 128 +
                                                 (ks * 16 + a_k8) * 2));
                ldsm4(ah[mt], aBase + aoff);
                if (PASSES == 2) ldsm4(al[mt], aBase + 16384 + aoff);
            }
#pragma unroll
            for (int ng = 0; ng < 4; ng++) {
                uint32_t boff = SW128((uint32_t)((wn + ng * 16 + b_row) * 128 +
                                                 (ks * 16 + b_k8) * 2));
                uint32_t b4[4];
                ldsm4(b4, bBase + boff);
#pragma unroll
                for (int mt = 0; mt < 2; mt++) {
                    mma_f16(acc[mt][ng * 2 + 0], ah[mt], b4[0], b4[1]);
                    if (PASSES == 2) mma_f16(acc[mt][ng * 2 + 0], al[mt], b4[0], b4[1]);
                    mma_f16(acc[mt][ng * 2 + 1], ah[mt], b4[2], b4[3]);
                    if (PASSES == 2) mma_f16(acc[mt][ng * 2 + 1], al[mt], b4[2], b4[3]);
                }
            }
        }
    };

    // ---- schedule: ONE __syncthreads per chunk (A double-buffered).
    issueB(0); CP_COMMIT();
    issueB(1); CP_COMMIT();
    issueB(2); CP_COMMIT();
    if (PASSES == 1) { issueB(3); CP_COMMIT(); }
    stageA(0);
#pragma unroll
    for (int c = 0; c < 4; c++) {
        commitA(c);
        if (c < 3) stageA(c + 1);
        if (PASSES == 1) {
            if (c == 0) cp_wait<3>(); else if (c == 1) cp_wait<2>();
            else if (c == 2) cp_wait<1>(); else cp_wait<0>();
        } else {
            if (c == 0) cp_wait<2>(); else if (c == 3) cp_wait<0>(); else cp_wait<1>();
        }
        __syncthreads();
        if (PASSES == 2 && c == 1) { issueB(3); CP_COMMIT(); }  // slot0 free now
        const int slot = (PASSES == 1) ? c : (c % 3);
        mma_chunk(sb + (c & 1) * ABUF, sb + BOFF + slot * 16384);
    }

    // ---- epilogue
    const int g = lane >> 2;
    const int cbase = bn + wn + (lane & 3) * 2;
    int prow[2][2];
    if (OUTHALF) {
#pragma unroll
        for (int mt = 0; mt < 2; mt++) {
            int r0 = bm + wm + mt * 16 + g;
            prow[mt][0] = (r0 < M) ? pad_row(r0) : 0;
            prow[mt][1] = (r0 + 8 < M) ? pad_row(r0 + 8) : 0;
        }
    }
#pragma unroll
    for (int nt = 0; nt < 8; nt++) {
        const int col = cbase + nt * 8;
        const float b0 = bias[col], b1 = bias[col + 1];
#pragma unroll
        for (int mt = 0; mt < 2; mt++) {
            int r0 = bm + wm + mt * 16 + g;
            if (r0 < M) {
                if (OUTHALF) {
                    __half2 hv = __floats2half2_rn(acc[mt][nt][0] + b0, acc[mt][nt][1] + b1);
                    *(__half2*)&Ch[(size_t)prow[mt][0] * 256 + col] = hv;
                } else {
                    *(float2*)&C[(size_t)r0 * N + col] =
                        make_float2(acc[mt][nt][0] + b0, acc[mt][nt][1] + b1);
                }
            }
            int r1 = r0 + 8;
            if (r1 < M) {
                if (OUTHALF) {
                    __half2 hv = __floats2half2_rn(acc[mt][nt][2] + b0, acc[mt][nt][3] + b1);
                    *(__half2*)&Ch[(size_t)prow[mt][1] * 256 + col] = hv;
                } else {
                    *(float2*)&C[(size_t)r1 * N + col] =
                        make_float2(acc[mt][nt][2] + b0, acc[mt][nt][3] + b1);
                }
            }
        }
    }
}

// ---------------------------------------------------------------------------
// Sampling kernel: smem-staged (weight, byte-offset) pairs (unchanged R9).
// ---------------------------------------------------------------------------
__global__ __launch_bounds__(256) void msda_sample(
    const __half* __restrict__ value,    // PADDED [45822,256] fp16
    const float* __restrict__ qout,      // [Lq,384] offsets|logits
    const float* __restrict__ rp,        // [Lq,4,2]
    __half* __restrict__ acch,
    __half* __restrict__ accl)
{
    constexpr int WW[4] = {180, 90, 45, 23};
    constexpr int PB[4] = {0, 33856, 42692, 45093};

    __shared__ uint2 swo[NHEADS][16][4];   // [head][point][corner] = {w, off}

    const int q = blockIdx.x;
    const int h = threadIdx.x >> 5;
    const int lane = threadIdx.x & 31;
    const int cr = lane >> 3;
    const int e  = lane & 7;

    float lg = -1e30f;
    if (lane < 16) lg = qout[q * 384 + 256 + h * 16 + lane];
    float m = lg;
#pragma unroll
    for (int s = 16; s > 0; s >>= 1)
        m = fmaxf(m, __shfl_xor_sync(0xffffffffu, m, s));
    float eo = (lane < 16) ? __expf(lg - m) : 0.f;
    float ssum = eo;
#pragma unroll
    for (int s = 16; s > 0; s >>= 1)
        ssum += __shfl_xor_sync(0xffffffffu, ssum, s);
    const float aw = eo / ssum;

    if (lane < 16) {
        const int l = lane >> 2;
        const int p = lane & 3;
        const int W = WW[l];
        const float rx = rp[(q * 4 + l) * 2 + 0];
        const float ry = rp[(q * 4 + l) * 2 + 1];
        const int oj = q * 384 + (((h * 4 + l) * 4) + p) * 2;
        const float x = fmaf(rx, (float)W, qout[oj + 0]) - 0.5f;
        const float y = fmaf(ry, (float)W, qout[oj + 1]) - 0.5f;
        const float xf = floorf(x), yf = floorf(y);
        const float dx = x - xf, dy = y - yf;
        const int xc = min(max((int)xf, -2), W);
        const int yc = min(max((int)yf, -2), W);
        const int B0 = (PB[l] + (yc + 2) * (W + 4) + (xc + 2)) * 512;
        const float wx1 = aw * dx;
        const float wx0 = aw - wx1;
#pragma unroll
        for (int c = 0; c < 4; c++) {
            const int cxx = c & 1, cyy = c >> 1;
            const int off = B0 + (cyy * (W + 4) + cxx) * 512;
            const float w = (cxx ? wx1 : wx0) * (cyy ? dy : (1.f - dy));
            swo[h][lane][c] = make_uint2(__float_as_uint(w), (uint32_t)off);
        }
    }
    __syncwarp();

    const char* __restrict__ vb = (const char*)value + h * 64 + e * 8;
    const uint2* __restrict__ sp = &swo[h][0][cr];
    float4 acc = make_float4(0.f, 0.f, 0.f, 0.f);

#pragma unroll
    for (int i = 0; i < 16; i++) {
        const uint2 wo = sp[i * 4];
        const float w = __uint_as_float(wo.x);
        const uint2 raw = *(const uint2*)(vb + wo.y);
        const float2 f0 = __half22float2(*(const __half2*)&raw.x);
        const float2 f1 = __half22float2(*(const __half2*)&raw.y);
        acc.x = fmaf(w, f0.x, acc.x);
        acc.y = fmaf(w, f0.y, acc.y);
        acc.z = fmaf(w, f1.x, acc.z);
        acc.w = fmaf(w, f1.y, acc.w);
    }

#pragma unroll
    for (int s = 8; s <= 16; s <<= 1) {
        acc.x += __shfl_xor_sync(0xffffffffu, acc.x, s);
        acc.y += __shfl_xor_sync(0xffffffffu, acc.y, s);
        acc.z += __shfl_xor_sync(0xffffffffu, acc.z, s);
        acc.w += __shfl_xor_sync(0xffffffffu, acc.w, s);
    }
    if (lane < 8) {
        float vals[4] = {acc.x, acc.y, acc.z, acc.w};
        uint32_t hiw[2], low[2];
#pragma unroll
        for (int i = 0; i < 2; i++) {
            float a0 = vals[2 * i], a1 = vals[2 * i + 1];
            float h0 = __half2float(__float2half_rn(a0));
            float h1 = __half2float(__float2half_rn(a1));
            hiw[i] = packh2(a0, a1);
            low[i] = packh2(a0 - h0, a1 - h1);
        }
        const size_t o = (size_t)q * 256 + h * 32 + lane * 4;
        *(uint2*)&acch[o] = make_uint2(hiw[0], hiw[1]);
        *(uint2*)&accl[o] = make_uint2(low[0], low[1]);
    }
}

// ---------------------------------------------------------------------------
// Launch
// ---------------------------------------------------------------------------
extern "C" void kernel_launch(void* const* d_in, const int* in_sizes, int n_in,
                              void* d_out, int out_size)
{
    const float* query    = (const float*)d_in[0];
    const float* value_in = (const float*)d_in[1];
    const float* rp       = (const float*)d_in[2];
    const float* Wv       = (const float*)d_in[3];
    const float* bv       = (const float*)d_in[4];
    const float* Ws       = (const float*)d_in[5];
    const float* bs       = (const float*)d_in[6];
    const float* Wa       = (const float*)d_in[7];
    const float* ba       = (const float*)d_in[8];
    const float* Wo       = (const float*)d_in[9];
    const float* bo       = (const float*)d_in[10];
    float* out = (float*)d_out;

    __half *pvh, *pah, *pal, *pwv, *pwq, *pwo;
    float *pq, *pbq;
    cudaGetSymbolAddress((void**)&pvh, g_value_h);
    cudaGetSymbolAddress((void**)&pq,  g_qout);
    cudaGetSymbolAddress((void**)&pah, g_acch);
    cudaGetSymbolAddress((void**)&pal, g_accl);
    cudaGetSymbolAddress((void**)&pbq, g_bq);
    cudaGetSymbolAddress((void**)&pwv, g_Wv);
    cudaGetSymbolAddress((void**)&pwq, g_Wq);
    cudaGetSymbolAddress((void**)&pwo, g_Wo);

    const int SMEM2 = 114688;  // PASSES=2: 64K A (2 bufs) + 48K B (3 slots)
    const int SMEM1 = 98304;   // PASSES=1: 32K A (2 bufs) + 64K B (4 slots)
    cudaFuncSetAttribute(gemm_mma<false, true, 2>,  cudaFuncAttributeMaxDynamicSharedMemorySize, SMEM2);
    cudaFuncSetAttribute(gemm_mma<false, false, 1>, cudaFuncAttributeMaxDynamicSharedMemorySize, SMEM1);
    cudaFuncSetAttribute(gemm_mma<true,  false, 2>, cudaFuncAttributeMaxDynamicSharedMemorySize, SMEM2);

    const int M = LQ;
    const int GBY = (M + 127) / 128;  // 337
    dim3 blk(256);

    // Combined prep (zero pads + weights + bias), single launch
    prep_all<<<(ZPN + 229760 + 255) / 256, 256>>>(Wv, Ws, Wa, Wo, bs, ba,
                                                  pvh, pwv, pwq, pwo, pbq);

    // value projection -> fp16 padded layout (split-2 for accuracy)
    gemm_mma<false, true, 2><<<dim3(2, GBY), blk, SMEM2>>>(
        value_in, nullptr, nullptr, pwv, bv, nullptr, pvh, M, 256);
    // merged offsets+logits projection (N=384), single-pass fp16
    gemm_mma<false, false, 1><<<dim3(3, GBY), blk, SMEM1>>>(
        query, nullptr, nullptr, pwq, pbq, pq, nullptr, M, 384);

    // Deformable sampling (padded gather, fp16 split out)
    msda_sample<<<M, 256>>>(pvh, pq, rp, pah, pal);

    // Output projection (A pre-split fp16, split-2)
    gemm_mma<true, false, 2><<<dim3(2, GBY), blk, SMEM2>>>(
        nullptr, pah, pal, pwo, bo, out, nullptr, M, 256);
}

// round 11
// speedup vs baseline: 1.1478x; 1.1478x over previous
#include <cuda_runtime.h>
#include <cuda_bf16.h>
#include <cuda_fp16.h>
#include <cstdint>

// Problem constants
#define LQ      43054
#define NHEADS  8

// Padded value geometry: each level padded +2 on every side.
#define PADROWS 45822
#define ZPN     (PADROWS * 16)

// Scratch (device globals; no runtime allocation allowed)
__device__ __half g_value_h[PADROWS * 256];     // projected value, fp16, PADDED
__device__ float  g_qout[LQ * 384];             // [0,256)=offsets, [256,384)=logits
__device__ __half g_acch[LQ * 256];             // msda out hi (fp16)
__device__ __half g_accl[LQ * 256];             // msda out lo (fp16 residual)
__device__ __half g_Wv[256 * 256];
__device__ __half g_Wq[384 * 256];              // merged Ws|Wa
__device__ __half g_Wo[256 * 256];
__device__ float g_bq[384];                     // merged bias bs|ba

#define SW128(o) ((o) ^ (((o) >> 3) & 0x70))

__device__ __forceinline__ uint32_t smem_u32(const void* p) {
    uint32_t a;
    asm("{ .reg .u64 t; cvta.to.shared.u64 t, %1; cvt.u32.u64 %0, t; }" : "=r"(a) : "l"(p));
    return a;
}
__device__ __forceinline__ void ldsm4(uint32_t r[4], uint32_t addr) {
    asm volatile("ldmatrix.sync.aligned.m8n8.x4.shared.b16 {%0,%1,%2,%3}, [%4];"
        : "=r"(r[0]), "=r"(r[1]), "=r"(r[2]), "=r"(r[3]) : "r"(addr));
}
__device__ __forceinline__ void mma_f16(float d[4], const uint32_t a[4],
                                        uint32_t b0, uint32_t b1) {
    asm volatile("mma.sync.aligned.m16n8k16.row.col.f32.f16.f16.f32 "
        "{%0,%1,%2,%3}, {%4,%5,%6,%7}, {%8,%9}, {%0,%1,%2,%3};"
        : "+f"(d[0]), "+f"(d[1]), "+f"(d[2]), "+f"(d[3])
        : "r"(a[0]), "r"(a[1]), "r"(a[2]), "r"(a[3]), "r"(b0), "r"(b1));
}
__device__ __forceinline__ uint32_t packh2(float x, float y) {
    __half2 h = __floats2half2_rn(x, y);
    return *(uint32_t*)&h;
}
__device__ __forceinline__ void cpa16(uint32_t d, const void* s) {
    asm volatile("cp.async.cg.shared.global [%0], [%1], 16;" :: "r"(d), "l"(s));
}
#define CP_COMMIT() asm volatile("cp.async.commit_group;" ::: "memory")
template <int Ngrp>
__device__ __forceinline__ void cp_wait() {
    asm volatile("cp.async.wait_group %0;" :: "n"(Ngrp) : "memory");
}

// Map original value row -> padded row index (compile-time divisors).
__device__ __forceinline__ int pad_row(int r) {
    if (r < 32400) { int cy = r / 180, cx = r - cy * 180; return (cy + 2) * 184 + cx + 2; }
    if (r < 40500) { int rr = r - 32400; int cy = rr / 90, cx = rr - cy * 90; return 33856 + (cy + 2) * 94 + cx + 2; }
    if (r < 42525) { int rr = r - 40500; int cy = rr / 45, cx = rr - cy * 45; return 42692 + (cy + 2) * 49 + cx + 2; }
    { int rr = r - 42525; int cy = rr / 23, cx = rr - cy * 23; return 45093 + (cy + 2) * 27 + cx + 2; }
}

// ---------------------------------------------------------------------------
// Combined prep: zero padding borders + fp16 weight transpose + merged bias.
// ---------------------------------------------------------------------------
__global__ __launch_bounds__(256) void prep_all(
    const float* __restrict__ Wv, const float* __restrict__ Ws,
    const float* __restrict__ Wa, const float* __restrict__ Wo,
    const float* __restrict__ bs, const float* __restrict__ ba,
    __half* __restrict__ vp,
    __half* __restrict__ wv, __half* __restrict__ wq, __half* __restrict__ wo,
    float* __restrict__ bq)
{
    int idx = blockIdx.x * 256 + threadIdx.x;
    if (idx < ZPN) {
        int row = idx >> 4, c = idx & 15;
        bool pad;
        if (row < 33856)      { int py = row / 184, px = row - py * 184;
                                pad = (py < 2) | (py >= 182) | (px < 2) | (px >= 182); }
        else if (row < 42692) { int r2 = row - 33856; int py = r2 / 94, px = r2 - py * 94;
                                pad = (py < 2) | (py >= 92) | (px < 2) | (px >= 92); }
        else if (row < 45093) { int r2 = row - 42692; int py = r2 / 49, px = r2 - py * 49;
                                pad = (py < 2) | (py >= 47) | (px < 2) | (px >= 47); }
        else                  { int r2 = row - 45093; int py = r2 / 27, px = r2 - py * 27;
                                pad = (py < 2) | (py >= 25) | (px < 2) | (px >= 25); }
        if (pad) {
            uint4* d = (uint4*)((char*)vp + (size_t)row * 512 + c * 32);
            d[0] = make_uint4(0, 0, 0, 0);
            d[1] = make_uint4(0, 0, 0, 0);
        }
        return;
    }
    idx -= ZPN;
    const float* W;
    __half* dst;
    int N, base, nofs;
    if (idx < 65536)        { W = Wv; dst = wv; N = 256; base = 0;      nofs = 0; }
    else if (idx < 131072)  { W = Ws; dst = wq; N = 256; base = 65536;  nofs = 0; }
    else if (idx < 163840)  { W = Wa; dst = wq; N = 128; base = 131072; nofs = 256; }
    else if (idx < 229376)  { W = Wo; dst = wo; N = 256; base = 163840; nofs = 0; }
    else if (idx < 229376 + 256) { bq[idx - 229376] = bs[idx - 229376]; return; }
    else if (idx < 229376 + 384) { bq[idx - 229376] = ba[idx - 229632]; return; }
    else return;
    int j = idx - base;
    int k = j / N, n = j % N + nofs;
    dst[n * 256 + k] = __float2half_rn(W[j]);
}

// ---------------------------------------------------------------------------
// Tensor-core GEMM, fp16, PASSES=1 or 2 (A split hi/lo). R9 schedule.
//   C[M,N] = A[M,256] @ W[256,N] + bias
// A register-staged, single smem buffer; B: 4 K-chunks prefetched up-front.
// CTA 128x128, 256 thr, 8 warps (4m x 2n), K chunks of 64.
// smem: A hi 0..16K [, A lo 16..32K], B chunk c at PASSES*16K + c*16K.
// ---------------------------------------------------------------------------
template <bool ASPLIT, bool OUTHALF, int PASSES>
__global__ __launch_bounds__(256, 2) void gemm_mma(
    const float* __restrict__ A,
    const __half* __restrict__ AhG,
    const __half* __restrict__ AlG,
    const __half* __restrict__ B,
    const float* __restrict__ bias,
    float* __restrict__ C,
    __half* __restrict__ Ch,
    int M, int N)
{
    extern __shared__ char smem[];
    const uint32_t sb = smem_u32(smem);
    constexpr int BOFF = PASSES * 16384;

    const int tid = threadIdx.x;
    const int wid = tid >> 5, lane = tid & 31;
    const int wm = (wid & 3) * 32;
    const int wn = (wid >> 2) * 64;
    const int bm = blockIdx.y * 128;
    const int bn = blockIdx.x * 128;

    float acc[2][8][4];
#pragma unroll
    for (int i = 0; i < 2; i++)
#pragma unroll
        for (int j = 0; j < 8; j++)
#pragma unroll
            for (int k = 0; k < 4; k++) acc[i][j][k] = 0.f;

    const int a_row = lane & 15;
    const int a_k8  = (lane >> 4) << 3;
    const int b_row = (lane & 7) + ((lane & 16) >> 1);
    const int b_k8  = lane & 8;

    const int ld_row = tid >> 1;          // 0..127
    const int ld_kh  = (tid & 1) * 32;    // 0 or 32 (k elements)
    const int grow   = bm + ld_row;
    const bool okA   = grow < M;

    auto issueB = [&](int c) {
        const int k0 = c * 64;
        const int n = bn + ld_row;
        const __half* s = &B[(size_t)n * 256 + k0 + ld_kh];
        const uint32_t bas = sb + BOFF + c * 16384;
#pragma unroll
        for (int jj = 0; jj < 4; jj++) {
            uint32_t off = SW128((uint32_t)(ld_row * 128 + (ld_kh + jj * 8) * 2));
            cpa16(bas + off, s + jj * 8);
        }
    };

    float4 vA[8];           // !ASPLIT
    uint4  sAh[4], sAl[4];  // ASPLIT
    auto stageA = [&](int c) {
        const int k0 = c * 64;
        if (!ASPLIT) {
            const float4* src = (const float4*)&A[(size_t)(okA ? grow : 0) * 256 + k0 + ld_kh];
#pragma unroll
            for (int j = 0; j < 8; j++)
                vA[j] = okA ? src[j] : make_float4(0.f, 0.f, 0.f, 0.f);
        } else {
            const uint4* sh = (const uint4*)&AhG[(size_t)(okA ? grow : 0) * 256 + k0 + ld_kh];
            const uint4* sl = (const uint4*)&AlG[(size_t)(okA ? grow : 0) * 256 + k0 + ld_kh];
#pragma unroll
            for (int j = 0; j < 4; j++) {
                sAh[j] = okA ? sh[j] : make_uint4(0, 0, 0, 0);
                sAl[j] = okA ? sl[j] : make_uint4(0, 0, 0, 0);
            }
        }
    };
    auto commitA = [&]() {
        if (!ASPLIT) {
#pragma unroll
            for (int jj = 0; jj < 4; jj++) {
                float4 v0 = vA[jj * 2 + 0];
                float4 v1 = vA[jj * 2 + 1];
                float vs[8] = {v0.x, v0.y, v0.z, v0.w, v1.x, v1.y, v1.z, v1.w};
                uint4 hi4, lo4;
                uint32_t* hp = (uint32_t*)&hi4;
                uint32_t* lp = (uint32_t*)&lo4;
#pragma unroll
                for (int i = 0; i < 4; i++) {
                    float a0 = vs[2 * i], a1 = vs[2 * i + 1];
                    hp[i] = packh2(a0, a1);
                    if (PASSES == 2) {
                        float h0 = __half2float(__float2half_rn(a0));
                        float h1 = __half2float(__float2half_rn(a1));
                        lp[i] = packh2(a0 - h0, a1 - h1);
                    }
                }
                uint32_t off = SW128((uint32_t)(ld_row * 128 + (ld_kh + jj * 8) * 2));
                *(uint4*)(smem + off) = hi4;
                if (PASSES == 2) *(uint4*)(smem + 16384 + off) = lo4;
            }
        } else {
#pragma unroll
            for (int jj = 0; jj < 4; jj++) {
                uint32_t off = SW128((uint32_t)(ld_row * 128 + (ld_kh + jj * 8) * 2));
                *(uint4*)(smem + off) = sAh[jj];
                if (PASSES == 2) *(uint4*)(smem + 16384 + off) = sAl[jj];
            }
        }
    };

    auto mma_chunk = [&](uint32_t bB) {
#pragma unroll
        for (int ks = 0; ks < 4; ks++) {
            uint32_t ah[2][4], al[2][4];
#pragma unroll
            for (int mt = 0; mt < 2; mt++) {
                uint32_t aoff = SW128((uint32_t)((wm + mt * 16 + a_row) * 128 +
                                                 (ks * 16 + a_k8) * 2));
                ldsm4(ah[mt], sb + aoff);
                if (PASSES == 2) ldsm4(al[mt], sb + 16384 + aoff);
            }
#pragma unroll
            for (int ng = 0; ng < 4; ng++) {
                uint32_t boff = SW128((uint32_t)((wn + ng * 16 + b_row) * 128 +
                                                 (ks * 16 + b_k8) * 2));
                uint32_t b4[4];
                ldsm4(b4, bB + boff);
#pragma unroll
                for (int mt = 0; mt < 2; mt++) {
                    mma_f16(acc[mt][ng * 2 + 0], ah[mt], b4[0], b4[1]);
                    if (PASSES == 2) mma_f16(acc[mt][ng * 2 + 0], al[mt], b4[0], b4[1]);
                    mma_f16(acc[mt][ng * 2 + 1], ah[mt], b4[2], b4[3]);
                    if (PASSES == 2) mma_f16(acc[mt][ng * 2 + 1], al[mt], b4[2], b4[3]);
                }
            }
        }
    };

    issueB(0); CP_COMMIT();
    issueB(1); CP_COMMIT();
    issueB(2); CP_COMMIT();
    issueB(3); CP_COMMIT();
    stageA(0);
#pragma unroll
    for (int c = 0; c < 4; c++) {
        if (c > 0) __syncthreads();          // mma(c-1) done before A overwrite
        commitA();
        if (c < 3) stageA(c + 1);
        if (c == 0) cp_wait<3>();
        else if (c == 1) cp_wait<2>();
        else if (c == 2) cp_wait<1>();
        else cp_wait<0>();
        __syncthreads();
        mma_chunk(sb + BOFF + c * 16384);
    }

    // ---- epilogue
    const int g = lane >> 2;
    const int cbase = bn + wn + (lane & 3) * 2;
    int prow[2][2];
    if (OUTHALF) {
#pragma unroll
        for (int mt = 0; mt < 2; mt++) {
            int r0 = bm + wm + mt * 16 + g;
            prow[mt][0] = (r0 < M) ? pad_row(r0) : 0;
            prow[mt][1] = (r0 + 8 < M) ? pad_row(r0 + 8) : 0;
        }
    }
#pragma unroll
    for (int nt = 0; nt < 8; nt++) {
        const int col = cbase + nt * 8;
        const float b0 = bias[col], b1 = bias[col + 1];
#pragma unroll
        for (int mt = 0; mt < 2; mt++) {
            int r0 = bm + wm + mt * 16 + g;
            if (r0 < M) {
                if (OUTHALF) {
                    __half2 hv = __floats2half2_rn(acc[mt][nt][0] + b0, acc[mt][nt][1] + b1);
                    *(__half2*)&Ch[(size_t)prow[mt][0] * 256 + col] = hv;
                } else {
                    *(float2*)&C[(size_t)r0 * N + col] =
                        make_float2(acc[mt][nt][0] + b0, acc[mt][nt][1] + b1);
                }
            }
            int r1 = r0 + 8;
            if (r1 < M) {
                if (OUTHALF) {
                    __half2 hv = __floats2half2_rn(acc[mt][nt][2] + b0, acc[mt][nt][3] + b1);
                    *(__half2*)&Ch[(size_t)prow[mt][1] * 256 + col] = hv;
                } else {
                    *(float2*)&C[(size_t)r1 * N + col] =
                        make_float2(acc[mt][nt][2] + b0, acc[mt][nt][3] + b1);
                }
            }
        }
    }
}

// ---------------------------------------------------------------------------
// Sampling kernel v6: 2 heads per warp, LDG.128 gathers.
// Block = 1 query, 128 threads (4 warps); warp w owns heads 2w, 2w+1.
// Lane = (h2:1)(cr:2)(e:2): h2 selects head, cr bilinear corner,
// e selects 16B (8 channels) of the 64B head row segment.
// Geometry: all 32 lanes busy (lane = h2*16 + point).
// ---------------------------------------------------------------------------
__global__ __launch_bounds__(128) void msda_sample(
    const __half* __restrict__ value,    // PADDED [45822,256] fp16
    const float* __restrict__ qout,      // [Lq,384] offsets|logits
    const float* __restrict__ rp,        // [Lq,4,2]
    __half* __restrict__ acch,
    __half* __restrict__ accl)
{
    constexpr int WW[4] = {180, 90, 45, 23};
    constexpr int PB[4] = {0, 33856, 42692, 45093};

    __shared__ uint2 swo[NHEADS][16][4];   // [head][point][corner] = {w, off}

    const int q = blockIdx.x;
    const int wid = threadIdx.x >> 5;      // 0..3
    const int lane = threadIdx.x & 31;
    const int h2 = lane >> 4;              // head within warp
    const int h  = wid * 2 + h2;
    const int pt = lane & 15;              // point for softmax/geometry
    const int cr = (lane >> 2) & 3;        // corner for gather
    const int e  = lane & 3;               // 16B channel group

    // ---- softmax: each lane owns one (h, pt) logit; reduce within 16-lane half
    const float lg = qout[q * 384 + 256 + h * 16 + pt];
    float m = lg;
#pragma unroll
    for (int s = 8; s > 0; s >>= 1)
        m = fmaxf(m, __shfl_xor_sync(0xffffffffu, m, s));
    const float eo = __expf(lg - m);
    float ssum = eo;
#pragma unroll
    for (int s = 8; s > 0; s >>= 1)
        ssum += __shfl_xor_sync(0xffffffffu, ssum, s);
    const float aw = eo / ssum;

    // ---- geometry: all 32 lanes (2 heads x 16 points)
    {
        const int l = pt >> 2;
        const int p = pt & 3;
        const int W = WW[l];
        const float rx = rp[(q * 4 + l) * 2 + 0];
        const float ry = rp[(q * 4 + l) * 2 + 1];
        const int oj = q * 384 + (((h * 4 + l) * 4) + p) * 2;
        const float x = fmaf(rx, (float)W, qout[oj + 0]) - 0.5f;
        const float y = fmaf(ry, (float)W, qout[oj + 1]) - 0.5f;
        const float xf = floorf(x), yf = floorf(y);
        const float dx = x - xf, dy = y - yf;
        const int xc = min(max((int)xf, -2), W);
        const int yc = min(max((int)yf, -2), W);
        const int B0 = (PB[l] + (yc + 2) * (W + 4) + (xc + 2)) * 512;
        const float wx1 = aw * dx;
        const float wx0 = aw - wx1;
#pragma unroll
        for (int c = 0; c < 4; c++) {
            const int cxx = c & 1, cyy = c >> 1;
            const int off = B0 + (cyy * (W + 4) + cxx) * 512;
            const float w = (cxx ? wx1 : wx0) * (cyy ? dy : (1.f - dy));
            swo[h][pt][c] = make_uint2(__float_as_uint(w), (uint32_t)off);
        }
    }
    __syncwarp();   // swo[h] written and read only by this warp

    // ---- gather: one LDG.128 per (point): 2 heads x 4 corners x 16B per instr
    const char* __restrict__ vb = (const char*)value + h * 64 + e * 16;
    const uint2* __restrict__ sp = &swo[h][0][cr];
    float acc[8];
#pragma unroll
    for (int j = 0; j < 8; j++) acc[j] = 0.f;

#pragma unroll
    for (int i = 0; i < 16; i++) {
        const uint2 wo = sp[i * 4];                  // LDS.64, imm offset
        const float w = __uint_as_float(wo.x);
        const uint4 raw = *(const uint4*)(vb + wo.y);
        const __half2* hp = (const __half2*)&raw;
#pragma unroll
        for (int j = 0; j < 4; j++) {
            const float2 f = __half22float2(hp[j]);
            acc[2 * j + 0] = fmaf(w, f.x, acc[2 * j + 0]);
            acc[2 * j + 1] = fmaf(w, f.y, acc[2 * j + 1]);
        }
    }

    // ---- reduce over the 4 corner groups (xor 4, 8; stays within head half)
#pragma unroll
    for (int s = 4; s <= 8; s <<= 1)
#pragma unroll
        for (int j = 0; j < 8; j++)
            acc[j] += __shfl_xor_sync(0xffffffffu, acc[j], s);

    if (cr == 0) {
        // lanes (h2, e): write channels [h*32 + e*8, +8) as fp16 hi/lo split
        uint4 hiw, low;
        uint32_t* hw = (uint32_t*)&hiw;
        uint32_t* lw = (uint32_t*)&low;
#pragma unroll
        for (int j = 0; j < 4; j++) {
            const float a0 = acc[2 * j], a1 = acc[2 * j + 1];
            const float r0 = __half2float(__float2half_rn(a0));
            const float r1 = __half2float(__float2half_rn(a1));
            hw[j] = packh2(a0, a1);
            lw[j] = packh2(a0 - r0, a1 - r1);
        }
        const size_t o = (size_t)q * 256 + h * 32 + e * 8;
        *(uint4*)&acch[o] = hiw;
        *(uint4*)&accl[o] = low;
    }
}

// ---------------------------------------------------------------------------
// Launch
// ---------------------------------------------------------------------------
extern "C" void kernel_launch(void* const* d_in, const int* in_sizes, int n_in,
                              void* d_out, int out_size)
{
    const float* query    = (const float*)d_in[0];
    const float* value_in = (const float*)d_in[1];
    const float* rp       = (const float*)d_in[2];
    const float* Wv       = (const float*)d_in[3];
    const float* bv       = (const float*)d_in[4];
    const float* Ws       = (const float*)d_in[5];
    const float* bs       = (const float*)d_in[6];
    const float* Wa       = (const float*)d_in[7];
    const float* ba       = (const float*)d_in[8];
    const float* Wo       = (const float*)d_in[9];
    const float* bo       = (const float*)d_in[10];
    float* out = (float*)d_out;

    __half *pvh, *pah, *pal, *pwv, *pwq, *pwo;
    float *pq, *pbq;
    cudaGetSymbolAddress((void**)&pvh, g_value_h);
    cudaGetSymbolAddress((void**)&pq,  g_qout);
    cudaGetSymbolAddress((void**)&pah, g_acch);
    cudaGetSymbolAddress((void**)&pal, g_accl);
    cudaGetSymbolAddress((void**)&pbq, g_bq);
    cudaGetSymbolAddress((void**)&pwv, g_Wv);
    cudaGetSymbolAddress((void**)&pwq, g_Wq);
    cudaGetSymbolAddress((void**)&pwo, g_Wo);

    const int SMEM2 = 98304;   // PASSES=2: 32K A + 64K B
    const int SMEM1 = 81920;   // PASSES=1: 16K A + 64K B
    cudaFuncSetAttribute(gemm_mma<false, true, 2>,  cudaFuncAttributeMaxDynamicSharedMemorySize, SMEM2);
    cudaFuncSetAttribute(gemm_mma<false, false, 1>, cudaFuncAttributeMaxDynamicSharedMemorySize, SMEM1);
    cudaFuncSetAttribute(gemm_mma<true,  false, 2>, cudaFuncAttributeMaxDynamicSharedMemorySize, SMEM2);

    const int M = LQ;
    const int GBY = (M + 127) / 128;  // 337
    dim3 blk(256);

    // Combined prep (zero pads + weights + bias), single launch
    prep_all<<<(ZPN + 229760 + 255) / 256, 256>>>(Wv, Ws, Wa, Wo, bs, ba,
                                                  pvh, pwv, pwq, pwo, pbq);

    // value projection -> fp16 padded layout (split-2 for accuracy)
    gemm_mma<false, true, 2><<<dim3(2, GBY), blk, SMEM2>>>(
        value_in, nullptr, nullptr, pwv, bv, nullptr, pvh, M, 256);
    // merged offsets+logits projection (N=384), single-pass fp16
    gemm_mma<false, false, 1><<<dim3(3, GBY), blk, SMEM1>>>(
        query, nullptr, nullptr, pwq, pbq, pq, nullptr, M, 384);

    // Deformable sampling: 128 threads/query, 2 heads per warp
    msda_sample<<<M, 128>>>(pvh, pq, rp, pah, pal);

    // Output projection (A pre-split fp16, split-2)
    gemm_mma<true, false, 2><<<dim3(2, GBY), blk, SMEM2>>>(
        nullptr, pah, pal, pwo, bo, out, nullptr, M, 256);
}

// round 12
// speedup vs baseline: 1.2229x; 1.0654x over previous
#include <cuda_runtime.h>
#include <cuda_bf16.h>
#include <cuda_fp16.h>
#include <cstdint>

// Problem constants
#define LQ      43054
#define NHEADS  8

// Padded value geometry: each level padded +2 on every side.
#define PADROWS 45822
#define ZPN     (PADROWS * 16)

// Scratch (device globals; no runtime allocation allowed)
__device__ __half g_value_h[PADROWS * 256];     // projected value, fp16, PADDED
__device__ float  g_qout[LQ * 384];             // [0,256)=offsets, [256,384)=logits
__device__ __half g_acc[LQ * 256];              // msda out (fp16)
__device__ __half g_Wv[256 * 256];
__device__ __half g_Wq[384 * 256];              // merged Ws|Wa
__device__ __half g_Wo[256 * 256];
__device__ float g_bq[384];                     // merged bias bs|ba

#define SW128(o) ((o) ^ (((o) >> 3) & 0x70))

__device__ __forceinline__ uint32_t smem_u32(const void* p) {
    uint32_t a;
    asm("{ .reg .u64 t; cvta.to.shared.u64 t, %1; cvt.u32.u64 %0, t; }" : "=r"(a) : "l"(p));
    return a;
}
__device__ __forceinline__ void ldsm4(uint32_t r[4], uint32_t addr) {
    asm volatile("ldmatrix.sync.aligned.m8n8.x4.shared.b16 {%0,%1,%2,%3}, [%4];"
        : "=r"(r[0]), "=r"(r[1]), "=r"(r[2]), "=r"(r[3]) : "r"(addr));
}
__device__ __forceinline__ void mma_f16(float d[4], const uint32_t a[4],
                                        uint32_t b0, uint32_t b1) {
    asm volatile("mma.sync.aligned.m16n8k16.row.col.f32.f16.f16.f32 "
        "{%0,%1,%2,%3}, {%4,%5,%6,%7}, {%8,%9}, {%0,%1,%2,%3};"
        : "+f"(d[0]), "+f"(d[1]), "+f"(d[2]), "+f"(d[3])
        : "r"(a[0]), "r"(a[1]), "r"(a[2]), "r"(a[3]), "r"(b0), "r"(b1));
}
__device__ __forceinline__ uint32_t packh2(float x, float y) {
    __half2 h = __floats2half2_rn(x, y);
    return *(uint32_t*)&h;
}
__device__ __forceinline__ void cpa16(uint32_t d, const void* s) {
    asm volatile("cp.async.cg.shared.global [%0], [%1], 16;" :: "r"(d), "l"(s));
}
#define CP_COMMIT() asm volatile("cp.async.commit_group;" ::: "memory")
template <int Ngrp>
__device__ __forceinline__ void cp_wait() {
    asm volatile("cp.async.wait_group %0;" :: "n"(Ngrp) : "memory");
}

// Map original value row -> padded row index (compile-time divisors).
__device__ __forceinline__ int pad_row(int r) {
    if (r < 32400) { int cy = r / 180, cx = r - cy * 180; return (cy + 2) * 184 + cx + 2; }
    if (r < 40500) { int rr = r - 32400; int cy = rr / 90, cx = rr - cy * 90; return 33856 + (cy + 2) * 94 + cx + 2; }
    if (r < 42525) { int rr = r - 40500; int cy = rr / 45, cx = rr - cy * 45; return 42692 + (cy + 2) * 49 + cx + 2; }
    { int rr = r - 42525; int cy = rr / 23, cx = rr - cy * 23; return 45093 + (cy + 2) * 27 + cx + 2; }
}

// ---------------------------------------------------------------------------
// Combined prep: zero padding borders + fp16 weight transpose + merged bias.
// ---------------------------------------------------------------------------
__global__ __launch_bounds__(256) void prep_all(
    const float* __restrict__ Wv, const float* __restrict__ Ws,
    const float* __restrict__ Wa, const float* __restrict__ Wo,
    const float* __restrict__ bs, const float* __restrict__ ba,
    __half* __restrict__ vp,
    __half* __restrict__ wv, __half* __restrict__ wq, __half* __restrict__ wo,
    float* __restrict__ bq)
{
    int idx = blockIdx.x * 256 + threadIdx.x;
    if (idx < ZPN) {
        int row = idx >> 4, c = idx & 15;
        bool pad;
        if (row < 33856)      { int py = row / 184, px = row - py * 184;
                                pad = (py < 2) | (py >= 182) | (px < 2) | (px >= 182); }
        else if (row < 42692) { int r2 = row - 33856; int py = r2 / 94, px = r2 - py * 94;
                                pad = (py < 2) | (py >= 92) | (px < 2) | (px >= 92); }
        else if (row < 45093) { int r2 = row - 42692; int py = r2 / 49, px = r2 - py * 49;
                                pad = (py < 2) | (py >= 47) | (px < 2) | (px >= 47); }
        else                  { int r2 = row - 45093; int py = r2 / 27, px = r2 - py * 27;
                                pad = (py < 2) | (py >= 25) | (px < 2) | (px >= 25); }
        if (pad) {
            uint4* d = (uint4*)((char*)vp + (size_t)row * 512 + c * 32);
            d[0] = make_uint4(0, 0, 0, 0);
            d[1] = make_uint4(0, 0, 0, 0);
        }
        return;
    }
    idx -= ZPN;
    const float* W;
    __half* dst;
    int N, base, nofs;
    if (idx < 65536)        { W = Wv; dst = wv; N = 256; base = 0;      nofs = 0; }
    else if (idx < 131072)  { W = Ws; dst = wq; N = 256; base = 65536;  nofs = 0; }
    else if (idx < 163840)  { W = Wa; dst = wq; N = 128; base = 131072; nofs = 256; }
    else if (idx < 229376)  { W = Wo; dst = wo; N = 256; base = 163840; nofs = 0; }
    else if (idx < 229376 + 256) { bq[idx - 229376] = bs[idx - 229376]; return; }
    else if (idx < 229376 + 384) { bq[idx - 229376] = ba[idx - 229632]; return; }
    else return;
    int j = idx - base;
    int k = j / N, n = j % N + nofs;
    dst[n * 256 + k] = __float2half_rn(W[j]);
}

// ---------------------------------------------------------------------------
// Tensor-core GEMM, fp16 single-pass (AHALF: A is fp16; else A fp32->fp16).
//   C[M,N] = A[M,256] @ W[256,N] + bias
// A register-staged, single smem buffer; B: 4 K-chunks prefetched up-front.
// CTA 128x128, 256 thr, 8 warps (4m x 2n), K chunks of 64.
// smem: A 0..16K, B chunk c at 16K + c*16K. Total 80KB -> 2 CTAs/SM.
// ---------------------------------------------------------------------------
template <bool AHALF, bool OUTHALF>
__global__ __launch_bounds__(256, 2) void gemm_mma(
    const float* __restrict__ A,
    const __half* __restrict__ AhG,
    const __half* __restrict__ B,
    const float* __restrict__ bias,
    float* __restrict__ C,
    __half* __restrict__ Ch,
    int M, int N)
{
    extern __shared__ char smem[];
    const uint32_t sb = smem_u32(smem);
    constexpr int BOFF = 16384;

    const int tid = threadIdx.x;
    const int wid = tid >> 5, lane = tid & 31;
    const int wm = (wid & 3) * 32;
    const int wn = (wid >> 2) * 64;
    const int bm = blockIdx.y * 128;
    const int bn = blockIdx.x * 128;

    float acc[2][8][4];
#pragma unroll
    for (int i = 0; i < 2; i++)
#pragma unroll
        for (int j = 0; j < 8; j++)
#pragma unroll
            for (int k = 0; k < 4; k++) acc[i][j][k] = 0.f;

    const int a_row = lane & 15;
    const int a_k8  = (lane >> 4) << 3;
    const int b_row = (lane & 7) + ((lane & 16) >> 1);
    const int b_k8  = lane & 8;

    const int ld_row = tid >> 1;          // 0..127
    const int ld_kh  = (tid & 1) * 32;    // 0 or 32 (k elements)
    const int grow   = bm + ld_row;
    const bool okA   = grow < M;

    auto issueB = [&](int c) {
        const int k0 = c * 64;
        const int n = bn + ld_row;
        const __half* s = &B[(size_t)n * 256 + k0 + ld_kh];
        const uint32_t bas = sb + BOFF + c * 16384;
#pragma unroll
        for (int jj = 0; jj < 4; jj++) {
            uint32_t off = SW128((uint32_t)(ld_row * 128 + (ld_kh + jj * 8) * 2));
            cpa16(bas + off, s + jj * 8);
        }
    };

    float4 vA[8];   // !AHALF
    uint4  sA[4];   // AHALF
    auto stageA = [&](int c) {
        const int k0 = c * 64;
        if (!AHALF) {
            const float4* src = (const float4*)&A[(size_t)(okA ? grow : 0) * 256 + k0 + ld_kh];
#pragma unroll
            for (int j = 0; j < 8; j++)
                vA[j] = okA ? src[j] : make_float4(0.f, 0.f, 0.f, 0.f);
        } else {
            const uint4* sh = (const uint4*)&AhG[(size_t)(okA ? grow : 0) * 256 + k0 + ld_kh];
#pragma unroll
            for (int j = 0; j < 4; j++)
                sA[j] = okA ? sh[j] : make_uint4(0, 0, 0, 0);
        }
    };
    auto commitA = [&]() {
        if (!AHALF) {
#pragma unroll
            for (int jj = 0; jj < 4; jj++) {
                float4 v0 = vA[jj * 2 + 0];
                float4 v1 = vA[jj * 2 + 1];
                uint4 hi4;
                uint32_t* hp = (uint32_t*)&hi4;
                hp[0] = packh2(v0.x, v0.y);
                hp[1] = packh2(v0.z, v0.w);
                hp[2] = packh2(v1.x, v1.y);
                hp[3] = packh2(v1.z, v1.w);
                uint32_t off = SW128((uint32_t)(ld_row * 128 + (ld_kh + jj * 8) * 2));
                *(uint4*)(smem + off) = hi4;
            }
        } else {
#pragma unroll
            for (int jj = 0; jj < 4; jj++) {
                uint32_t off = SW128((uint32_t)(ld_row * 128 + (ld_kh + jj * 8) * 2));
                *(uint4*)(smem + off) = sA[jj];
            }
        }
    };

    auto mma_chunk = [&](uint32_t bB) {
#pragma unroll
        for (int ks = 0; ks < 4; ks++) {
            uint32_t ah[2][4];
#pragma unroll
            for (int mt = 0; mt < 2; mt++) {
                uint32_t aoff = SW128((uint32_t)((wm + mt * 16 + a_row) * 128 +
                                                 (ks * 16 + a_k8) * 2));
                ldsm4(ah[mt], sb + aoff);
            }
#pragma unroll
            for (int ng = 0; ng < 4; ng++) {
                uint32_t boff = SW128((uint32_t)((wn + ng * 16 + b_row) * 128 +
                                                 (ks * 16 + b_k8) * 2));
                uint32_t b4[4];
                ldsm4(b4, bB + boff);
#pragma unroll
                for (int mt = 0; mt < 2; mt++) {
                    mma_f16(acc[mt][ng * 2 + 0], ah[mt], b4[0], b4[1]);
                    mma_f16(acc[mt][ng * 2 + 1], ah[mt], b4[2], b4[3]);
                }
            }
        }
    };

    issueB(0); CP_COMMIT();
    issueB(1); CP_COMMIT();
    issueB(2); CP_COMMIT();
    issueB(3); CP_COMMIT();
    stageA(0);
#pragma unroll
    for (int c = 0; c < 4; c++) {
        if (c > 0) __syncthreads();          // mma(c-1) done before A overwrite
        commitA();
        if (c < 3) stageA(c + 1);
        if (c == 0) cp_wait<3>();
        else if (c == 1) cp_wait<2>();
        else if (c == 2) cp_wait<1>();
        else cp_wait<0>();
        __syncthreads();
        mma_chunk(sb + BOFF + c * 16384);
    }

    // ---- epilogue
    const int g = lane >> 2;
    const int cbase = bn + wn + (lane & 3) * 2;
    int prow[2][2];
    if (OUTHALF) {
#pragma unroll
        for (int mt = 0; mt < 2; mt++) {
            int r0 = bm + wm + mt * 16 + g;
            prow[mt][0] = (r0 < M) ? pad_row(r0) : 0;
            prow[mt][1] = (r0 + 8 < M) ? pad_row(r0 + 8) : 0;
        }
    }
#pragma unroll
    for (int nt = 0; nt < 8; nt++) {
        const int col = cbase + nt * 8;
        const float b0 = bias[col], b1 = bias[col + 1];
#pragma unroll
        for (int mt = 0; mt < 2; mt++) {
            int r0 = bm + wm + mt * 16 + g;
            if (r0 < M) {
                if (OUTHALF) {
                    __half2 hv = __floats2half2_rn(acc[mt][nt][0] + b0, acc[mt][nt][1] + b1);
                    *(__half2*)&Ch[(size_t)prow[mt][0] * 256 + col] = hv;
                } else {
                    *(float2*)&C[(size_t)r0 * N + col] =
                        make_float2(acc[mt][nt][0] + b0, acc[mt][nt][1] + b1);
                }
            }
            int r1 = r0 + 8;
            if (r1 < M) {
                if (OUTHALF) {
                    __half2 hv = __floats2half2_rn(acc[mt][nt][2] + b0, acc[mt][nt][3] + b1);
                    *(__half2*)&Ch[(size_t)prow[mt][1] * 256 + col] = hv;
                } else {
                    *(float2*)&C[(size_t)r1 * N + col] =
                        make_float2(acc[mt][nt][2] + b0, acc[mt][nt][3] + b1);
                }
            }
        }
    }
}

// ---------------------------------------------------------------------------
// Sampling kernel: 2 heads per warp, LDG.128 gathers, plain fp16 output.
// Block = 1 query, 128 threads (4 warps); warp w owns heads 2w, 2w+1.
// ---------------------------------------------------------------------------
__global__ __launch_bounds__(128) void msda_sample(
    const __half* __restrict__ value,    // PADDED [45822,256] fp16
    const float* __restrict__ qout,      // [Lq,384] offsets|logits
    const float* __restrict__ rp,        // [Lq,4,2]
    __half* __restrict__ accb)
{
    constexpr int WW[4] = {180, 90, 45, 23};
    constexpr int PB[4] = {0, 33856, 42692, 45093};

    __shared__ uint2 swo[NHEADS][16][4];   // [head][point][corner] = {w, off}

    const int q = blockIdx.x;
    const int wid = threadIdx.x >> 5;      // 0..3
    const int lane = threadIdx.x & 31;
    const int h2 = lane >> 4;              // head within warp
    const int h  = wid * 2 + h2;
    const int pt = lane & 15;              // point for softmax/geometry
    const int cr = (lane >> 2) & 3;        // corner for gather
    const int e  = lane & 3;               // 16B channel group

    // ---- softmax: each lane owns one (h, pt) logit; reduce within 16-lane half
    const float lg = qout[q * 384 + 256 + h * 16 + pt];
    float m = lg;
#pragma unroll
    for (int s = 8; s > 0; s >>= 1)
        m = fmaxf(m, __shfl_xor_sync(0xffffffffu, m, s));
    const float eo = __expf(lg - m);
    float ssum = eo;
#pragma unroll
    for (int s = 8; s > 0; s >>= 1)
        ssum += __shfl_xor_sync(0xffffffffu, ssum, s);
    const float aw = eo / ssum;

    // ---- geometry: all 32 lanes (2 heads x 16 points)
    {
        const int l = pt >> 2;
        const int p = pt & 3;
        const int W = WW[l];
        const float rx = rp[(q * 4 + l) * 2 + 0];
        const float ry = rp[(q * 4 + l) * 2 + 1];
        const int oj = q * 384 + (((h * 4 + l) * 4) + p) * 2;
        const float x = fmaf(rx, (float)W, qout[oj + 0]) - 0.5f;
        const float y = fmaf(ry, (float)W, qout[oj + 1]) - 0.5f;
        const float xf = floorf(x), yf = floorf(y);
        const float dx = x - xf, dy = y - yf;
        const int xc = min(max((int)xf, -2), W);
        const int yc = min(max((int)yf, -2), W);
        const int B0 = (PB[l] + (yc + 2) * (W + 4) + (xc + 2)) * 512;
        const float wx1 = aw * dx;
        const float wx0 = aw - wx1;
#pragma unroll
        for (int c = 0; c < 4; c++) {
            const int cxx = c & 1, cyy = c >> 1;
            const int off = B0 + (cyy * (W + 4) + cxx) * 512;
            const float w = (cxx ? wx1 : wx0) * (cyy ? dy : (1.f - dy));
            swo[h][pt][c] = make_uint2(__float_as_uint(w), (uint32_t)off);
        }
    }
    __syncwarp();   // swo[h] written and read only by this warp

    // ---- gather: one LDG.128 per point per lane
    const char* __restrict__ vb = (const char*)value + h * 64 + e * 16;
    const uint2* __restrict__ sp = &swo[h][0][cr];
    float acc[8];
#pragma unroll
    for (int j = 0; j < 8; j++) acc[j] = 0.f;

#pragma unroll
    for (int i = 0; i < 16; i++) {
        const uint2 wo = sp[i * 4];                  // LDS.64, imm offset
        const float w = __uint_as_float(wo.x);
        const uint4 raw = *(const uint4*)(vb + wo.y);
        const __half2* hp = (const __half2*)&raw;
#pragma unroll
        for (int j = 0; j < 4; j++) {
            const float2 f = __half22float2(hp[j]);
            acc[2 * j + 0] = fmaf(w, f.x, acc[2 * j + 0]);
            acc[2 * j + 1] = fmaf(w, f.y, acc[2 * j + 1]);
        }
    }

    // ---- reduce over the 4 corner groups (xor 4, 8; stays within head half)
#pragma unroll
    for (int s = 4; s <= 8; s <<= 1)
#pragma unroll
        for (int j = 0; j < 8; j++)
            acc[j] += __shfl_xor_sync(0xffffffffu, acc[j], s);

    if (cr == 0) {
        uint4 hv;
        uint32_t* hw = (uint32_t*)&hv;
#pragma unroll
        for (int j = 0; j < 4; j++)
            hw[j] = packh2(acc[2 * j], acc[2 * j + 1]);
        const size_t o = (size_t)q * 256 + h * 32 + e * 8;
        *(uint4*)&accb[o] = hv;
    }
}

// ---------------------------------------------------------------------------
// Launch
// ---------------------------------------------------------------------------
extern "C" void kernel_launch(void* const* d_in, const int* in_sizes, int n_in,
                              void* d_out, int out_size)
{
    const float* query    = (const float*)d_in[0];
    const float* value_in = (const float*)d_in[1];
    const float* rp       = (const float*)d_in[2];
    const float* Wv       = (const float*)d_in[3];
    const float* bv       = (const float*)d_in[4];
    const float* Ws       = (const float*)d_in[5];
    const float* bs       = (const float*)d_in[6];
    const float* Wa       = (const float*)d_in[7];
    const float* ba       = (const float*)d_in[8];
    const float* Wo       = (const float*)d_in[9];
    const float* bo       = (const float*)d_in[10];
    float* out = (float*)d_out;

    __half *pvh, *pac, *pwv, *pwq, *pwo;
    float *pq, *pbq;
    cudaGetSymbolAddress((void**)&pvh, g_value_h);
    cudaGetSymbolAddress((void**)&pq,  g_qout);
    cudaGetSymbolAddress((void**)&pac, g_acc);
    cudaGetSymbolAddress((void**)&pbq, g_bq);
    cudaGetSymbolAddress((void**)&pwv, g_Wv);
    cudaGetSymbolAddress((void**)&pwq, g_Wq);
    cudaGetSymbolAddress((void**)&pwo, g_Wo);

    const int SMEM = 81920;   // 16K A + 64K B -> 2 CTAs/SM
    cudaFuncSetAttribute(gemm_mma<false, true>,  cudaFuncAttributeMaxDynamicSharedMemorySize, SMEM);
    cudaFuncSetAttribute(gemm_mma<false, false>, cudaFuncAttributeMaxDynamicSharedMemorySize, SMEM);
    cudaFuncSetAttribute(gemm_mma<true,  false>, cudaFuncAttributeMaxDynamicSharedMemorySize, SMEM);

    const int M = LQ;
    const int GBY = (M + 127) / 128;  // 337
    dim3 blk(256);

    // Combined prep (zero pads + weights + bias), single launch
    prep_all<<<(ZPN + 229760 + 255) / 256, 256>>>(Wv, Ws, Wa, Wo, bs, ba,
                                                  pvh, pwv, pwq, pwo, pbq);

    // value projection -> fp16 padded layout (single-pass)
    gemm_mma<false, true><<<dim3(2, GBY), blk, SMEM>>>(
        value_in, nullptr, pwv, bv, nullptr, pvh, M, 256);
    // merged offsets+logits projection (N=384), single-pass
    gemm_mma<false, false><<<dim3(3, GBY), blk, SMEM>>>(
        query, nullptr, pwq, pbq, pq, nullptr, M, 384);

    // Deformable sampling: 128 threads/query, 2 heads per warp, fp16 out
    msda_sample<<<M, 128>>>(pvh, pq, rp, pac);

    // Output projection (A fp16 direct, single-pass)
    gemm_mma<true, false><<<dim3(2, GBY), blk, SMEM>>>(
        nullptr, pac, pwo, bo, out, nullptr, M, 256);
}

// round 13
// speedup vs baseline: 1.2994x; 1.0626x over previous
#include <cuda_runtime.h>
#include <cuda_bf16.h>
#include <cuda_fp16.h>
#include <cstdint>

// Problem constants
#define LQ      43054
#define NHEADS  8

// Padded value geometry: each level padded +2 on every side.
#define PADROWS 45822
#define ZPN     (PADROWS * 16)

// Scratch (device globals; no runtime allocation allowed)
__device__ __half g_value_h[PADROWS * 256];     // projected value, fp16, PADDED
__device__ float  g_qout[LQ * 384];             // [0,256)=offsets, [256,384)=logits
__device__ __half g_acc[LQ * 256];              // msda out (fp16)
__device__ __half g_Wv[256 * 256];
__device__ __half g_Wq[384 * 256];              // merged Ws|Wa
__device__ __half g_Wo[256 * 256];
__device__ float g_bq[384];                     // merged bias bs|ba

#define SW128(o) ((o) ^ (((o) >> 3) & 0x70))

__device__ __forceinline__ uint32_t smem_u32(const void* p) {
    uint32_t a;
    asm("{ .reg .u64 t; cvta.to.shared.u64 t, %1; cvt.u32.u64 %0, t; }" : "=r"(a) : "l"(p));
    return a;
}
__device__ __forceinline__ void ldsm4(uint32_t r[4], uint32_t addr) {
    asm volatile("ldmatrix.sync.aligned.m8n8.x4.shared.b16 {%0,%1,%2,%3}, [%4];"
        : "=r"(r[0]), "=r"(r[1]), "=r"(r[2]), "=r"(r[3]) : "r"(addr));
}
__device__ __forceinline__ void mma_f16(float d[4], const uint32_t a[4],
                                        uint32_t b0, uint32_t b1) {
    asm volatile("mma.sync.aligned.m16n8k16.row.col.f32.f16.f16.f32 "
        "{%0,%1,%2,%3}, {%4,%5,%6,%7}, {%8,%9}, {%0,%1,%2,%3};"
        : "+f"(d[0]), "+f"(d[1]), "+f"(d[2]), "+f"(d[3])
        : "r"(a[0]), "r"(a[1]), "r"(a[2]), "r"(a[3]), "r"(b0), "r"(b1));
}
__device__ __forceinline__ uint32_t packh2(float x, float y) {
    __half2 h = __floats2half2_rn(x, y);
    return *(uint32_t*)&h;
}
__device__ __forceinline__ void cpa16(uint32_t d, const void* s) {
    asm volatile("cp.async.cg.shared.global [%0], [%1], 16;" :: "r"(d), "l"(s));
}
#define CP_COMMIT() asm volatile("cp.async.commit_group;" ::: "memory")
template <int Ngrp>
__device__ __forceinline__ void cp_wait() {
    asm volatile("cp.async.wait_group %0;" :: "n"(Ngrp) : "memory");
}

// Map original value row -> padded row index (compile-time divisors).
__device__ __forceinline__ int pad_row(int r) {
    if (r < 32400) { int cy = r / 180, cx = r - cy * 180; return (cy + 2) * 184 + cx + 2; }
    if (r < 40500) { int rr = r - 32400; int cy = rr / 90, cx = rr - cy * 90; return 33856 + (cy + 2) * 94 + cx + 2; }
    if (r < 42525) { int rr = r - 40500; int cy = rr / 45, cx = rr - cy * 45; return 42692 + (cy + 2) * 49 + cx + 2; }
    { int rr = r - 42525; int cy = rr / 23, cx = rr - cy * 23; return 45093 + (cy + 2) * 27 + cx + 2; }
}

// ---------------------------------------------------------------------------
// Combined prep: zero padding borders + fp16 weight transpose + merged bias.
// ---------------------------------------------------------------------------
__global__ __launch_bounds__(256) void prep_all(
    const float* __restrict__ Wv, const float* __restrict__ Ws,
    const float* __restrict__ Wa, const float* __restrict__ Wo,
    const float* __restrict__ bs, const float* __restrict__ ba,
    __half* __restrict__ vp,
    __half* __restrict__ wv, __half* __restrict__ wq, __half* __restrict__ wo,
    float* __restrict__ bq)
{
    int idx = blockIdx.x * 256 + threadIdx.x;
    if (idx < ZPN) {
        int row = idx >> 4, c = idx & 15;
        bool pad;
        if (row < 33856)      { int py = row / 184, px = row - py * 184;
                                pad = (py < 2) | (py >= 182) | (px < 2) | (px >= 182); }
        else if (row < 42692) { int r2 = row - 33856; int py = r2 / 94, px = r2 - py * 94;
                                pad = (py < 2) | (py >= 92) | (px < 2) | (px >= 92); }
        else if (row < 45093) { int r2 = row - 42692; int py = r2 / 49, px = r2 - py * 49;
                                pad = (py < 2) | (py >= 47) | (px < 2) | (px >= 47); }
        else                  { int r2 = row - 45093; int py = r2 / 27, px = r2 - py * 27;
                                pad = (py < 2) | (py >= 25) | (px < 2) | (px >= 25); }
        if (pad) {
            uint4* d = (uint4*)((char*)vp + (size_t)row * 512 + c * 32);
            d[0] = make_uint4(0, 0, 0, 0);
            d[1] = make_uint4(0, 0, 0, 0);
        }
        return;
    }
    idx -= ZPN;
    const float* W;
    __half* dst;
    int N, base, nofs;
    if (idx < 65536)        { W = Wv; dst = wv; N = 256; base = 0;      nofs = 0; }
    else if (idx < 131072)  { W = Ws; dst = wq; N = 256; base = 65536;  nofs = 0; }
    else if (idx < 163840)  { W = Wa; dst = wq; N = 128; base = 131072; nofs = 256; }
    else if (idx < 229376)  { W = Wo; dst = wo; N = 256; base = 163840; nofs = 0; }
    else if (idx < 229376 + 256) { bq[idx - 229376] = bs[idx - 229376]; return; }
    else if (idx < 229376 + 384) { bq[idx - 229376] = ba[idx - 229632]; return; }
    else return;
    int j = idx - base;
    int k = j / N, n = j % N + nofs;
    dst[n * 256 + k] = __float2half_rn(W[j]);
}

// ===========================================================================
// GEMM common body pieces (shared by proj_fused and gemm_out via macros of
// identical structure). CTA 128x128, 256 thr, 8 warps (4m x 2n), K=256 in 4
// chunks of 64. smem: A 0..16K, B chunk c at 16K + c*16K (80KB, 2 CTAs/SM).
// ===========================================================================

// ---------------------------------------------------------------------------
// Fused projection kernel: one launch does BOTH
//   bx<2 : value path  Cv[pad] (fp16) = value_in @ Wv + bv
//   bx>=2: q path      Cq (fp32, N=384) = query @ Wq + bq
// ---------------------------------------------------------------------------
__global__ __launch_bounds__(256, 2) void proj_fused(
    const float* __restrict__ Av, const float* __restrict__ Aq,
    const __half* __restrict__ Bv, const __half* __restrict__ Bq,
    const float* __restrict__ biasv, const float* __restrict__ biasq,
    __half* __restrict__ Cv, float* __restrict__ Cq, int M)
{
    extern __shared__ char smem[];
    const uint32_t sb = smem_u32(smem);
    constexpr int BOFF = 16384;

    const bool vpath = blockIdx.x < 2;
    const int bn = (vpath ? blockIdx.x : blockIdx.x - 2) * 128;
    const float* __restrict__ A = vpath ? Av : Aq;
    const __half* __restrict__ B = vpath ? Bv : Bq;
    const float* __restrict__ bias = vpath ? biasv : biasq;

    const int tid = threadIdx.x;
    const int wid = tid >> 5, lane = tid & 31;
    const int wm = (wid & 3) * 32;
    const int wn = (wid >> 2) * 64;
    const int bm = blockIdx.y * 128;

    float acc[2][8][4];
#pragma unroll
    for (int i = 0; i < 2; i++)
#pragma unroll
        for (int j = 0; j < 8; j++)
#pragma unroll
            for (int k = 0; k < 4; k++) acc[i][j][k] = 0.f;

    const int a_row = lane & 15;
    const int a_k8  = (lane >> 4) << 3;
    const int b_row = (lane & 7) + ((lane & 16) >> 1);
    const int b_k8  = lane & 8;

    const int ld_row = tid >> 1;
    const int ld_kh  = (tid & 1) * 32;
    const int grow   = bm + ld_row;
    const bool okA   = grow < M;

    auto issueB = [&](int c) {
        const int k0 = c * 64;
        const int n = bn + ld_row;
        const __half* s = &B[(size_t)n * 256 + k0 + ld_kh];
        const uint32_t bas = sb + BOFF + c * 16384;
#pragma unroll
        for (int jj = 0; jj < 4; jj++) {
            uint32_t off = SW128((uint32_t)(ld_row * 128 + (ld_kh + jj * 8) * 2));
            cpa16(bas + off, s + jj * 8);
        }
    };

    float4 vA[8];
    auto stageA = [&](int c) {
        const int k0 = c * 64;
        const float4* src = (const float4*)&A[(size_t)(okA ? grow : 0) * 256 + k0 + ld_kh];
#pragma unroll
        for (int j = 0; j < 8; j++)
            vA[j] = okA ? src[j] : make_float4(0.f, 0.f, 0.f, 0.f);
    };
    auto commitA = [&]() {
#pragma unroll
        for (int jj = 0; jj < 4; jj++) {
            float4 v0 = vA[jj * 2 + 0];
            float4 v1 = vA[jj * 2 + 1];
            uint4 hi4;
            uint32_t* hp = (uint32_t*)&hi4;
            hp[0] = packh2(v0.x, v0.y);
            hp[1] = packh2(v0.z, v0.w);
            hp[2] = packh2(v1.x, v1.y);
            hp[3] = packh2(v1.z, v1.w);
            uint32_t off = SW128((uint32_t)(ld_row * 128 + (ld_kh + jj * 8) * 2));
            *(uint4*)(smem + off) = hi4;
        }
    };

    auto mma_chunk = [&](uint32_t bB) {
#pragma unroll
        for (int ks = 0; ks < 4; ks++) {
            uint32_t ah[2][4];
#pragma unroll
            for (int mt = 0; mt < 2; mt++) {
                uint32_t aoff = SW128((uint32_t)((wm + mt * 16 + a_row) * 128 +
                                                 (ks * 16 + a_k8) * 2));
                ldsm4(ah[mt], sb + aoff);
            }
#pragma unroll
            for (int ng = 0; ng < 4; ng++) {
                uint32_t boff = SW128((uint32_t)((wn + ng * 16 + b_row) * 128 +
                                                 (ks * 16 + b_k8) * 2));
                uint32_t b4[4];
                ldsm4(b4, bB + boff);
#pragma unroll
                for (int mt = 0; mt < 2; mt++) {
                    mma_f16(acc[mt][ng * 2 + 0], ah[mt], b4[0], b4[1]);
                    mma_f16(acc[mt][ng * 2 + 1], ah[mt], b4[2], b4[3]);
                }
            }
        }
    };

    issueB(0); CP_COMMIT();
    issueB(1); CP_COMMIT();
    issueB(2); CP_COMMIT();
    issueB(3); CP_COMMIT();
    stageA(0);
#pragma unroll
    for (int c = 0; c < 4; c++) {
        if (c > 0) __syncthreads();
        commitA();
        if (c < 3) stageA(c + 1);
        if (c == 0) cp_wait<3>();
        else if (c == 1) cp_wait<2>();
        else if (c == 2) cp_wait<1>();
        else cp_wait<0>();
        __syncthreads();
        mma_chunk(sb + BOFF + c * 16384);
    }

    // epilogue
    const int g = lane >> 2;
    const int cb = wn + (lane & 3) * 2;
    if (vpath) {
        int prow[2][2];
#pragma unroll
        for (int mt = 0; mt < 2; mt++) {
            int r0 = bm + wm + mt * 16 + g;
            prow[mt][0] = (r0 < M) ? pad_row(r0) : 0;
            prow[mt][1] = (r0 + 8 < M) ? pad_row(r0 + 8) : 0;
        }
#pragma unroll
        for (int nt = 0; nt < 8; nt++) {
            const int col = bn + cb + nt * 8;
            const float b0 = bias[col], b1 = bias[col + 1];
#pragma unroll
            for (int mt = 0; mt < 2; mt++) {
                int r0 = bm + wm + mt * 16 + g;
                if (r0 < M)
                    *(__half2*)&Cv[(size_t)prow[mt][0] * 256 + col] =
                        __floats2half2_rn(acc[mt][nt][0] + b0, acc[mt][nt][1] + b1);
                if (r0 + 8 < M)
                    *(__half2*)&Cv[(size_t)prow[mt][1] * 256 + col] =
                        __floats2half2_rn(acc[mt][nt][2] + b0, acc[mt][nt][3] + b1);
            }
        }
    } else {
#pragma unroll
        for (int nt = 0; nt < 8; nt++) {
            const int col = bn + cb + nt * 8;
            const float b0 = bias[col], b1 = bias[col + 1];
#pragma unroll
            for (int mt = 0; mt < 2; mt++) {
                int r0 = bm + wm + mt * 16 + g;
                if (r0 < M)
                    *(float2*)&Cq[(size_t)r0 * 384 + col] =
                        make_float2(acc[mt][nt][0] + b0, acc[mt][nt][1] + b1);
                if (r0 + 8 < M)
                    *(float2*)&Cq[(size_t)(r0 + 8) * 384 + col] =
                        make_float2(acc[mt][nt][2] + b0, acc[mt][nt][3] + b1);
            }
        }
    }
}

// ---------------------------------------------------------------------------
// Output GEMM: out (fp32, N=256) = acc (fp16) @ Wo + bo
// ---------------------------------------------------------------------------
__global__ __launch_bounds__(256, 2) void gemm_out(
    const __half* __restrict__ AhG,
    const __half* __restrict__ B,
    const float* __restrict__ bias,
    float* __restrict__ C, int M)
{
    extern __shared__ char smem[];
    const uint32_t sb = smem_u32(smem);
    constexpr int BOFF = 16384;

    const int tid = threadIdx.x;
    const int wid = tid >> 5, lane = tid & 31;
    const int wm = (wid & 3) * 32;
    const int wn = (wid >> 2) * 64;
    const int bm = blockIdx.y * 128;
    const int bn = blockIdx.x * 128;

    float acc[2][8][4];
#pragma unroll
    for (int i = 0; i < 2; i++)
#pragma unroll
        for (int j = 0; j < 8; j++)
#pragma unroll
            for (int k = 0; k < 4; k++) acc[i][j][k] = 0.f;

    const int a_row = lane & 15;
    const int a_k8  = (lane >> 4) << 3;
    const int b_row = (lane & 7) + ((lane & 16) >> 1);
    const int b_k8  = lane & 8;

    const int ld_row = tid >> 1;
    const int ld_kh  = (tid & 1) * 32;
    const int grow   = bm + ld_row;
    const bool okA   = grow < M;

    auto issueB = [&](int c) {
        const int k0 = c * 64;
        const int n = bn + ld_row;
        const __half* s = &B[(size_t)n * 256 + k0 + ld_kh];
        const uint32_t bas = sb + BOFF + c * 16384;
#pragma unroll
        for (int jj = 0; jj < 4; jj++) {
            uint32_t off = SW128((uint32_t)(ld_row * 128 + (ld_kh + jj * 8) * 2));
            cpa16(bas + off, s + jj * 8);
        }
    };

    uint4 sA[4];
    auto stageA = [&](int c) {
        const int k0 = c * 64;
        const uint4* sh = (const uint4*)&AhG[(size_t)(okA ? grow : 0) * 256 + k0 + ld_kh];
#pragma unroll
        for (int j = 0; j < 4; j++)
            sA[j] = okA ? sh[j] : make_uint4(0, 0, 0, 0);
    };
    auto commitA = [&]() {
#pragma unroll
        for (int jj = 0; jj < 4; jj++) {
            uint32_t off = SW128((uint32_t)(ld_row * 128 + (ld_kh + jj * 8) * 2));
            *(uint4*)(smem + off) = sA[jj];
        }
    };

    auto mma_chunk = [&](uint32_t bB) {
#pragma unroll
        for (int ks = 0; ks < 4; ks++) {
            uint32_t ah[2][4];
#pragma unroll
            for (int mt = 0; mt < 2; mt++) {
                uint32_t aoff = SW128((uint32_t)((wm + mt * 16 + a_row) * 128 +
                                                 (ks * 16 + a_k8) * 2));
                ldsm4(ah[mt], sb + aoff);
            }
#pragma unroll
            for (int ng = 0; ng < 4; ng++) {
                uint32_t boff = SW128((uint32_t)((wn + ng * 16 + b_row) * 128 +
                                                 (ks * 16 + b_k8) * 2));
                uint32_t b4[4];
                ldsm4(b4, bB + boff);
#pragma unroll
                for (int mt = 0; mt < 2; mt++) {
                    mma_f16(acc[mt][ng * 2 + 0], ah[mt], b4[0], b4[1]);
                    mma_f16(acc[mt][ng * 2 + 1], ah[mt], b4[2], b4[3]);
                }
            }
        }
    };

    issueB(0); CP_COMMIT();
    issueB(1); CP_COMMIT();
    issueB(2); CP_COMMIT();
    issueB(3); CP_COMMIT();
    stageA(0);
#pragma unroll
    for (int c = 0; c < 4; c++) {
        if (c > 0) __syncthreads();
        commitA();
        if (c < 3) stageA(c + 1);
        if (c == 0) cp_wait<3>();
        else if (c == 1) cp_wait<2>();
        else if (c == 2) cp_wait<1>();
        else cp_wait<0>();
        __syncthreads();
        mma_chunk(sb + BOFF + c * 16384);
    }

    const int g = lane >> 2;
    const int cbase = bn + wn + (lane & 3) * 2;
#pragma unroll
    for (int nt = 0; nt < 8; nt++) {
        const int col = cbase + nt * 8;
        const float b0 = bias[col], b1 = bias[col + 1];
#pragma unroll
        for (int mt = 0; mt < 2; mt++) {
            int r0 = bm + wm + mt * 16 + g;
            if (r0 < M)
                *(float2*)&C[(size_t)r0 * 256 + col] =
                    make_float2(acc[mt][nt][0] + b0, acc[mt][nt][1] + b1);
            if (r0 + 8 < M)
                *(float2*)&C[(size_t)(r0 + 8) * 256 + col] =
                    make_float2(acc[mt][nt][2] + b0, acc[mt][nt][3] + b1);
        }
    }
}

// ---------------------------------------------------------------------------
// Sampling kernel: 2 queries per block (256 thr), 2 heads per warp,
// LDG.128 gathers, fp16 output.
// ---------------------------------------------------------------------------
__global__ __launch_bounds__(256) void msda_sample(
    const __half* __restrict__ value,    // PADDED [45822,256] fp16
    const float* __restrict__ qout,      // [Lq,384] offsets|logits
    const float* __restrict__ rp,        // [Lq,4,2]
    __half* __restrict__ accb)
{
    constexpr int WW[4] = {180, 90, 45, 23};
    constexpr int PB[4] = {0, 33856, 42692, 45093};

    __shared__ uint2 swo[2][NHEADS][16][4];   // [q-half][head][point][corner]

    const int tid = threadIdx.x;
    const int qi = tid >> 7;               // query within block
    const int q = blockIdx.x * 2 + qi;
    const int t7 = tid & 127;
    const int wid = t7 >> 5;               // 0..3
    const int lane = tid & 31;
    const int h2 = lane >> 4;
    const int h  = wid * 2 + h2;
    const int pt = lane & 15;
    const int cr = (lane >> 2) & 3;
    const int e  = lane & 3;

    // softmax over this head's 16 logits (lane owns (h, pt))
    const float lg = qout[q * 384 + 256 + h * 16 + pt];
    float m = lg;
#pragma unroll
    for (int s = 8; s > 0; s >>= 1)
        m = fmaxf(m, __shfl_xor_sync(0xffffffffu, m, s));
    const float eo = __expf(lg - m);
    float ssum = eo;
#pragma unroll
    for (int s = 8; s > 0; s >>= 1)
        ssum += __shfl_xor_sync(0xffffffffu, ssum, s);
    const float aw = eo / ssum;

    // geometry: all 32 lanes (2 heads x 16 points)
    {
        const int l = pt >> 2;
        const int p = pt & 3;
        const int W = WW[l];
        const float2 rxy = *(const float2*)&rp[(q * 4 + l) * 2];
        const int oj = q * 384 + (((h * 4 + l) * 4) + p) * 2;
        const float2 oxy = *(const float2*)&qout[oj];
        const float x = fmaf(rxy.x, (float)W, oxy.x) - 0.5f;
        const float y = fmaf(rxy.y, (float)W, oxy.y) - 0.5f;
        const float xf = floorf(x), yf = floorf(y);
        const float dx = x - xf, dy = y - yf;
        const int xc = min(max((int)xf, -2), W);
        const int yc = min(max((int)yf, -2), W);
        const int B0 = (PB[l] + (yc + 2) * (W + 4) + (xc + 2)) * 512;
        const float wx1 = aw * dx;
        const float wx0 = aw - wx1;
#pragma unroll
        for (int c = 0; c < 4; c++) {
            const int cxx = c & 1, cyy = c >> 1;
            const int off = B0 + (cyy * (W + 4) + cxx) * 512;
            const float w = (cxx ? wx1 : wx0) * (cyy ? dy : (1.f - dy));
            swo[qi][h][pt][c] = make_uint2(__float_as_uint(w), (uint32_t)off);
        }
    }
    __syncwarp();   // swo[qi][h] written and read only by this warp

    // gather: one LDG.128 per point per lane
    const char* __restrict__ vb = (const char*)value + h * 64 + e * 16;
    const uint2* __restrict__ sp = &swo[qi][h][0][cr];
    float acc[8];
#pragma unroll
    for (int j = 0; j < 8; j++) acc[j] = 0.f;

#pragma unroll
    for (int i = 0; i < 16; i++) {
        const uint2 wo = sp[i * 4];
        const float w = __uint_as_float(wo.x);
        const uint4 raw = *(const uint4*)(vb + wo.y);
        const __half2* hp = (const __half2*)&raw;
#pragma unroll
        for (int j = 0; j < 4; j++) {
            const float2 f = __half22float2(hp[j]);
            acc[2 * j + 0] = fmaf(w, f.x, acc[2 * j + 0]);
            acc[2 * j + 1] = fmaf(w, f.y, acc[2 * j + 1]);
        }
    }

    // reduce over corner groups (xor 4, 8 stays within head half)
#pragma unroll
    for (int s = 4; s <= 8; s <<= 1)
#pragma unroll
        for (int j = 0; j < 8; j++)
            acc[j] += __shfl_xor_sync(0xffffffffu, acc[j], s);

    if (cr == 0) {
        uint4 hv;
        uint32_t* hw = (uint32_t*)&hv;
#pragma unroll
        for (int j = 0; j < 4; j++)
            hw[j] = packh2(acc[2 * j], acc[2 * j + 1]);
        const size_t o = (size_t)q * 256 + h * 32 + e * 8;
        *(uint4*)&accb[o] = hv;
    }
}

// ---------------------------------------------------------------------------
// Launch
// ---------------------------------------------------------------------------
extern "C" void kernel_launch(void* const* d_in, const int* in_sizes, int n_in,
                              void* d_out, int out_size)
{
    const float* query    = (const float*)d_in[0];
    const float* value_in = (const float*)d_in[1];
    const float* rp       = (const float*)d_in[2];
    const float* Wv       = (const float*)d_in[3];
    const float* bv       = (const float*)d_in[4];
    const float* Ws       = (const float*)d_in[5];
    const float* bs       = (const float*)d_in[6];
    const float* Wa       = (const float*)d_in[7];
    const float* ba       = (const float*)d_in[8];
    const float* Wo       = (const float*)d_in[9];
    const float* bo       = (const float*)d_in[10];
    float* out = (float*)d_out;

    __half *pvh, *pac, *pwv, *pwq, *pwo;
    float *pq, *pbq;
    cudaGetSymbolAddress((void**)&pvh, g_value_h);
    cudaGetSymbolAddress((void**)&pq,  g_qout);
    cudaGetSymbolAddress((void**)&pac, g_acc);
    cudaGetSymbolAddress((void**)&pbq, g_bq);
    cudaGetSymbolAddress((void**)&pwv, g_Wv);
    cudaGetSymbolAddress((void**)&pwq, g_Wq);
    cudaGetSymbolAddress((void**)&pwo, g_Wo);

    const int SMEM = 81920;   // 16K A + 64K B -> 2 CTAs/SM
    cudaFuncSetAttribute(proj_fused, cudaFuncAttributeMaxDynamicSharedMemorySize, SMEM);
    cudaFuncSetAttribute(gemm_out,   cudaFuncAttributeMaxDynamicSharedMemorySize, SMEM);

    const int M = LQ;
    const int GBY = (M + 127) / 128;  // 337
    dim3 blk(256);

    // Combined prep (zero pads + weights + bias), single launch
    prep_all<<<(ZPN + 229760 + 255) / 256, 256>>>(Wv, Ws, Wa, Wo, bs, ba,
                                                  pvh, pwv, pwq, pwo, pbq);

    // Fused value + offsets/logits projections (one launch)
    proj_fused<<<dim3(5, GBY), blk, SMEM>>>(
        value_in, query, pwv, pwq, bv, pbq, pvh, pq, M);

    // Deformable sampling: 2 queries/block, 2 heads/warp
    msda_sample<<<LQ / 2, 256>>>(pvh, pq, rp, pac);

    // Output projection
    gemm_out<<<dim3(2, GBY), blk, SMEM>>>(pac, pwo, bo, out, M);
}

// round 14
// speedup vs baseline: 1.4291x; 1.0998x over previous
#include <cuda_runtime.h>
#include <cuda_bf16.h>
#include <cuda_fp16.h>
#include <cstdint>

// Problem constants
#define LQ      43054
#define NHEADS  8

// Padded value geometry: each level padded +2 on every side.
#define PADROWS 45822
#define ZPN     (PADROWS * 8)     // one zero-task per (pixel, head)

// Scratch (device globals; no runtime allocation allowed)
// Head-major padded value: [head][padded pixel][32 fp16] (64B per pixel-head)
__device__ __half g_value_h[NHEADS * PADROWS * 32];
__device__ float  g_qout[LQ * 384];             // [0,256)=offsets, [256,384)=logits
__device__ __half g_acc[LQ * 256];              // msda out (fp16)
__device__ __half g_Wv[256 * 256];
__device__ __half g_Wq[384 * 256];              // merged Ws|Wa
__device__ __half g_Wo[256 * 256];
__device__ float g_bq[384];                     // merged bias bs|ba

#define SW128(o) ((o) ^ (((o) >> 3) & 0x70))

__device__ __forceinline__ uint32_t smem_u32(const void* p) {
    uint32_t a;
    asm("{ .reg .u64 t; cvta.to.shared.u64 t, %1; cvt.u32.u64 %0, t; }" : "=r"(a) : "l"(p));
    return a;
}
__device__ __forceinline__ void ldsm4(uint32_t r[4], uint32_t addr) {
    asm volatile("ldmatrix.sync.aligned.m8n8.x4.shared.b16 {%0,%1,%2,%3}, [%4];"
        : "=r"(r[0]), "=r"(r[1]), "=r"(r[2]), "=r"(r[3]) : "r"(addr));
}
__device__ __forceinline__ void mma_f16(float d[4], const uint32_t a[4],
                                        uint32_t b0, uint32_t b1) {
    asm volatile("mma.sync.aligned.m16n8k16.row.col.f32.f16.f16.f32 "
        "{%0,%1,%2,%3}, {%4,%5,%6,%7}, {%8,%9}, {%0,%1,%2,%3};"
        : "+f"(d[0]), "+f"(d[1]), "+f"(d[2]), "+f"(d[3])
        : "r"(a[0]), "r"(a[1]), "r"(a[2]), "r"(a[3]), "r"(b0), "r"(b1));
}
__device__ __forceinline__ uint32_t packh2(float x, float y) {
    __half2 h = __floats2half2_rn(x, y);
    return *(uint32_t*)&h;
}
__device__ __forceinline__ void cpa16(uint32_t d, const void* s) {
    asm volatile("cp.async.cg.shared.global [%0], [%1], 16;" :: "r"(d), "l"(s));
}
#define CP_COMMIT() asm volatile("cp.async.commit_group;" ::: "memory")
template <int Ngrp>
__device__ __forceinline__ void cp_wait() {
    asm volatile("cp.async.wait_group %0;" :: "n"(Ngrp) : "memory");
}

// Map original value row -> padded row index (compile-time divisors).
__device__ __forceinline__ int pad_row(int r) {
    if (r < 32400) { int cy = r / 180, cx = r - cy * 180; return (cy + 2) * 184 + cx + 2; }
    if (r < 40500) { int rr = r - 32400; int cy = rr / 90, cx = rr - cy * 90; return 33856 + (cy + 2) * 94 + cx + 2; }
    if (r < 42525) { int rr = r - 40500; int cy = rr / 45, cx = rr - cy * 45; return 42692 + (cy + 2) * 49 + cx + 2; }
    { int rr = r - 42525; int cy = rr / 23, cx = rr - cy * 23; return 45093 + (cy + 2) * 27 + cx + 2; }
}

// ---------------------------------------------------------------------------
// Combined prep: zero padding borders (head-major) + fp16 weights + bias.
// ---------------------------------------------------------------------------
__global__ __launch_bounds__(256) void prep_all(
    const float* __restrict__ Wv, const float* __restrict__ Ws,
    const float* __restrict__ Wa, const float* __restrict__ Wo,
    const float* __restrict__ bs, const float* __restrict__ ba,
    __half* __restrict__ vp,
    __half* __restrict__ wv, __half* __restrict__ wq, __half* __restrict__ wo,
    float* __restrict__ bq)
{
    int idx = blockIdx.x * 256 + threadIdx.x;
    if (idx < ZPN) {
        int row = idx >> 3, h = idx & 7;
        bool pad;
        if (row < 33856)      { int py = row / 184, px = row - py * 184;
                                pad = (py < 2) | (py >= 182) | (px < 2) | (px >= 182); }
        else if (row < 42692) { int r2 = row - 33856; int py = r2 / 94, px = r2 - py * 94;
                                pad = (py < 2) | (py >= 92) | (px < 2) | (px >= 92); }
        else if (row < 45093) { int r2 = row - 42692; int py = r2 / 49, px = r2 - py * 49;
                                pad = (py < 2) | (py >= 47) | (px < 2) | (px >= 47); }
        else                  { int r2 = row - 45093; int py = r2 / 27, px = r2 - py * 27;
                                pad = (py < 2) | (py >= 25) | (px < 2) | (px >= 25); }
        if (pad) {
            uint4* d = (uint4*)((char*)vp + ((size_t)h * PADROWS + row) * 64);
            d[0] = make_uint4(0, 0, 0, 0);
            d[1] = make_uint4(0, 0, 0, 0);
            d[2] = make_uint4(0, 0, 0, 0);
            d[3] = make_uint4(0, 0, 0, 0);
        }
        return;
    }
    idx -= ZPN;
    const float* W;
    __half* dst;
    int N, base, nofs;
    if (idx < 65536)        { W = Wv; dst = wv; N = 256; base = 0;      nofs = 0; }
    else if (idx < 131072)  { W = Ws; dst = wq; N = 256; base = 65536;  nofs = 0; }
    else if (idx < 163840)  { W = Wa; dst = wq; N = 128; base = 131072; nofs = 256; }
    else if (idx < 229376)  { W = Wo; dst = wo; N = 256; base = 163840; nofs = 0; }
    else if (idx < 229376 + 256) { bq[idx - 229376] = bs[idx - 229376]; return; }
    else if (idx < 229376 + 384) { bq[idx - 229376] = ba[idx - 229632]; return; }
    else return;
    int j = idx - base;
    int k = j / N, n = j % N + nofs;
    dst[n * 256 + k] = __float2half_rn(W[j]);
}

// ---------------------------------------------------------------------------
// Fused projection kernel: one launch does BOTH
//   bx<2 : value path  -> head-major padded fp16 value
//   bx>=2: q path      -> fp32 [Lq,384] offsets|logits
// ---------------------------------------------------------------------------
__global__ __launch_bounds__(256, 2) void proj_fused(
    const float* __restrict__ Av, const float* __restrict__ Aq,
    const __half* __restrict__ Bv, const __half* __restrict__ Bq,
    const float* __restrict__ biasv, const float* __restrict__ biasq,
    __half* __restrict__ Cv, float* __restrict__ Cq, int M)
{
    extern __shared__ char smem[];
    const uint32_t sb = smem_u32(smem);
    constexpr int BOFF = 16384;

    const bool vpath = blockIdx.x < 2;
    const int bn = (vpath ? blockIdx.x : blockIdx.x - 2) * 128;
    const float* __restrict__ A = vpath ? Av : Aq;
    const __half* __restrict__ B = vpath ? Bv : Bq;
    const float* __restrict__ bias = vpath ? biasv : biasq;

    const int tid = threadIdx.x;
    const int wid = tid >> 5, lane = tid & 31;
    const int wm = (wid & 3) * 32;
    const int wn = (wid >> 2) * 64;
    const int bm = blockIdx.y * 128;

    float acc[2][8][4];
#pragma unroll
    for (int i = 0; i < 2; i++)
#pragma unroll
        for (int j = 0; j < 8; j++)
#pragma unroll
            for (int k = 0; k < 4; k++) acc[i][j][k] = 0.f;

    const int a_row = lane & 15;
    const int a_k8  = (lane >> 4) << 3;
    const int b_row = (lane & 7) + ((lane & 16) >> 1);
    const int b_k8  = lane & 8;

    const int ld_row = tid >> 1;
    const int ld_kh  = (tid & 1) * 32;
    const int grow   = bm + ld_row;
    const bool okA   = grow < M;

    auto issueB = [&](int c) {
        const int k0 = c * 64;
        const int n = bn + ld_row;
        const __half* s = &B[(size_t)n * 256 + k0 + ld_kh];
        const uint32_t bas = sb + BOFF + c * 16384;
#pragma unroll
        for (int jj = 0; jj < 4; jj++) {
            uint32_t off = SW128((uint32_t)(ld_row * 128 + (ld_kh + jj * 8) * 2));
            cpa16(bas + off, s + jj * 8);
        }
    };

    float4 vA[8];
    auto stageA = [&](int c) {
        const int k0 = c * 64;
        const float4* src = (const float4*)&A[(size_t)(okA ? grow : 0) * 256 + k0 + ld_kh];
#pragma unroll
        for (int j = 0; j < 8; j++)
            vA[j] = okA ? src[j] : make_float4(0.f, 0.f, 0.f, 0.f);
    };
    auto commitA = [&]() {
#pragma unroll
        for (int jj = 0; jj < 4; jj++) {
            float4 v0 = vA[jj * 2 + 0];
            float4 v1 = vA[jj * 2 + 1];
            uint4 hi4;
            uint32_t* hp = (uint32_t*)&hi4;
            hp[0] = packh2(v0.x, v0.y);
            hp[1] = packh2(v0.z, v0.w);
            hp[2] = packh2(v1.x, v1.y);
            hp[3] = packh2(v1.z, v1.w);
            uint32_t off = SW128((uint32_t)(ld_row * 128 + (ld_kh + jj * 8) * 2));
            *(uint4*)(smem + off) = hi4;
        }
    };

    auto mma_chunk = [&](uint32_t bB) {
#pragma unroll
        for (int ks = 0; ks < 4; ks++) {
            uint32_t ah[2][4];
#pragma unroll
            for (int mt = 0; mt < 2; mt++) {
                uint32_t aoff = SW128((uint32_t)((wm + mt * 16 + a_row) * 128 +
                                                 (ks * 16 + a_k8) * 2));
                ldsm4(ah[mt], sb + aoff);
            }
#pragma unroll
            for (int ng = 0; ng < 4; ng++) {
                uint32_t boff = SW128((uint32_t)((wn + ng * 16 + b_row) * 128 +
                                                 (ks * 16 + b_k8) * 2));
                uint32_t b4[4];
                ldsm4(b4, bB + boff);
#pragma unroll
                for (int mt = 0; mt < 2; mt++) {
                    mma_f16(acc[mt][ng * 2 + 0], ah[mt], b4[0], b4[1]);
                    mma_f16(acc[mt][ng * 2 + 1], ah[mt], b4[2], b4[3]);
                }
            }
        }
    };

    issueB(0); CP_COMMIT();
    issueB(1); CP_COMMIT();
    issueB(2); CP_COMMIT();
    issueB(3); CP_COMMIT();
    stageA(0);
#pragma unroll
    for (int c = 0; c < 4; c++) {
        if (c > 0) __syncthreads();
        commitA();
        if (c < 3) stageA(c + 1);
        if (c == 0) cp_wait<3>();
        else if (c == 1) cp_wait<2>();
        else if (c == 2) cp_wait<1>();
        else cp_wait<0>();
        __syncthreads();
        mma_chunk(sb + BOFF + c * 16384);
    }

    // epilogue
    const int g = lane >> 2;
    const int cb = wn + (lane & 3) * 2;
    if (vpath) {
        int prow[2][2];
#pragma unroll
        for (int mt = 0; mt < 2; mt++) {
            int r0 = bm + wm + mt * 16 + g;
            prow[mt][0] = (r0 < M) ? pad_row(r0) : 0;
            prow[mt][1] = (r0 + 8 < M) ? pad_row(r0 + 8) : 0;
        }
#pragma unroll
        for (int nt = 0; nt < 8; nt++) {
            const int col = bn + cb + nt * 8;
            const int hh = col >> 5, ch = col & 31;
            const float b0 = bias[col], b1 = bias[col + 1];
#pragma unroll
            for (int mt = 0; mt < 2; mt++) {
                int r0 = bm + wm + mt * 16 + g;
                if (r0 < M)
                    *(__half2*)&Cv[((size_t)hh * PADROWS + prow[mt][0]) * 32 + ch] =
                        __floats2half2_rn(acc[mt][nt][0] + b0, acc[mt][nt][1] + b1);
                if (r0 + 8 < M)
                    *(__half2*)&Cv[((size_t)hh * PADROWS + prow[mt][1]) * 32 + ch] =
                        __floats2half2_rn(acc[mt][nt][2] + b0, acc[mt][nt][3] + b1);
            }
        }
    } else {
#pragma unroll
        for (int nt = 0; nt < 8; nt++) {
            const int col = bn + cb + nt * 8;
            const float b0 = bias[col], b1 = bias[col + 1];
#pragma unroll
            for (int mt = 0; mt < 2; mt++) {
                int r0 = bm + wm + mt * 16 + g;
                if (r0 < M)
                    *(float2*)&Cq[(size_t)r0 * 384 + col] =
                        make_float2(acc[mt][nt][0] + b0, acc[mt][nt][1] + b1);
                if (r0 + 8 < M)
                    *(float2*)&Cq[(size_t)(r0 + 8) * 384 + col] =
                        make_float2(acc[mt][nt][2] + b0, acc[mt][nt][3] + b1);
            }
        }
    }
}

// ---------------------------------------------------------------------------
// Output GEMM: out (fp32, N=256) = acc (fp16) @ Wo + bo
// ---------------------------------------------------------------------------
__global__ __launch_bounds__(256, 2) void gemm_out(
    const __half* __restrict__ AhG,
    const __half* __restrict__ B,
    const float* __restrict__ bias,
    float* __restrict__ C, int M)
{
    extern __shared__ char smem[];
    const uint32_t sb = smem_u32(smem);
    constexpr int BOFF = 16384;

    const int tid = threadIdx.x;
    const int wid = tid >> 5, lane = tid & 31;
    const int wm = (wid & 3) * 32;
    const int wn = (wid >> 2) * 64;
    const int bm = blockIdx.y * 128;
    const int bn = blockIdx.x * 128;

    float acc[2][8][4];
#pragma unroll
    for (int i = 0; i < 2; i++)
#pragma unroll
        for (int j = 0; j < 8; j++)
#pragma unroll
            for (int k = 0; k < 4; k++) acc[i][j][k] = 0.f;

    const int a_row = lane & 15;
    const int a_k8  = (lane >> 4) << 3;
    const int b_row = (lane & 7) + ((lane & 16) >> 1);
    const int b_k8  = lane & 8;

    const int ld_row = tid >> 1;
    const int ld_kh  = (tid & 1) * 32;
    const int grow   = bm + ld_row;
    const bool okA   = grow < M;

    auto issueB = [&](int c) {
        const int k0 = c * 64;
        const int n = bn + ld_row;
        const __half* s = &B[(size_t)n * 256 + k0 + ld_kh];
        const uint32_t bas = sb + BOFF + c * 16384;
#pragma unroll
        for (int jj = 0; jj < 4; jj++) {
            uint32_t off = SW128((uint32_t)(ld_row * 128 + (ld_kh + jj * 8) * 2));
            cpa16(bas + off, s + jj * 8);
        }
    };

    uint4 sA[4];
    auto stageA = [&](int c) {
        const int k0 = c * 64;
        const uint4* sh = (const uint4*)&AhG[(size_t)(okA ? grow : 0) * 256 + k0 + ld_kh];
#pragma unroll
        for (int j = 0; j < 4; j++)
            sA[j] = okA ? sh[j] : make_uint4(0, 0, 0, 0);
    };
    auto commitA = [&]() {
#pragma unroll
        for (int jj = 0; jj < 4; jj++) {
            uint32_t off = SW128((uint32_t)(ld_row * 128 + (ld_kh + jj * 8) * 2));
            *(uint4*)(smem + off) = sA[jj];
        }
    };

    auto mma_chunk = [&](uint32_t bB) {
#pragma unroll
        for (int ks = 0; ks < 4; ks++) {
            uint32_t ah[2][4];
#pragma unroll
            for (int mt = 0; mt < 2; mt++) {
                uint32_t aoff = SW128((uint32_t)((wm + mt * 16 + a_row) * 128 +
                                                 (ks * 16 + a_k8) * 2));
                ldsm4(ah[mt], sb + aoff);
            }
#pragma unroll
            for (int ng = 0; ng < 4; ng++) {
                uint32_t boff = SW128((uint32_t)((wn + ng * 16 + b_row) * 128 +
                                                 (ks * 16 + b_k8) * 2));
                uint32_t b4[4];
                ldsm4(b4, bB + boff);
#pragma unroll
                for (int mt = 0; mt < 2; mt++) {
                    mma_f16(acc[mt][ng * 2 + 0], ah[mt], b4[0], b4[1]);
                    mma_f16(acc[mt][ng * 2 + 1], ah[mt], b4[2], b4[3]);
                }
            }
        }
    };

    issueB(0); CP_COMMIT();
    issueB(1); CP_COMMIT();
    issueB(2); CP_COMMIT();
    issueB(3); CP_COMMIT();
    stageA(0);
#pragma unroll
    for (int c = 0; c < 4; c++) {
        if (c > 0) __syncthreads();
        commitA();
        if (c < 3) stageA(c + 1);
        if (c == 0) cp_wait<3>();
        else if (c == 1) cp_wait<2>();
        else if (c == 2) cp_wait<1>();
        else cp_wait<0>();
        __syncthreads();
        mma_chunk(sb + BOFF + c * 16384);
    }

    const int g = lane >> 2;
    const int cbase = bn + wn + (lane & 3) * 2;
#pragma unroll
    for (int nt = 0; nt < 8; nt++) {
        const int col = cbase + nt * 8;
        const float b0 = bias[col], b1 = bias[col + 1];
#pragma unroll
        for (int mt = 0; mt < 2; mt++) {
            int r0 = bm + wm + mt * 16 + g;
            if (r0 < M)
                *(float2*)&C[(size_t)r0 * 256 + col] =
                    make_float2(acc[mt][nt][0] + b0, acc[mt][nt][1] + b1);
            if (r0 + 8 < M)
                *(float2*)&C[(size_t)(r0 + 8) * 256 + col] =
                    make_float2(acc[mt][nt][2] + b0, acc[mt][nt][3] + b1);
        }
    }
}

// ---------------------------------------------------------------------------
// Sampling kernel: head-major value layout. 2 queries/block, 2 heads/warp.
// Per head, a pixel's 32 channels = contiguous 64B; x-corner pairs are
// adjacent pixels -> contiguous 128B -> high L1 line utilization.
// ---------------------------------------------------------------------------
__global__ __launch_bounds__(256) void msda_sample(
    const __half* __restrict__ value,    // [8][PADROWS][32] fp16
    const float* __restrict__ qout,      // [Lq,384] offsets|logits
    const float* __restrict__ rp,        // [Lq,4,2]
    __half* __restrict__ accb)
{
    constexpr int WW[4] = {180, 90, 45, 23};
    constexpr int PB[4] = {0, 33856, 42692, 45093};

    __shared__ uint2 swo[2][NHEADS][16][4];   // [q-half][head][point][corner]

    const int tid = threadIdx.x;
    const int qi = tid >> 7;
    const int q = blockIdx.x * 2 + qi;
    const int t7 = tid & 127;
    const int wid = t7 >> 5;
    const int lane = tid & 31;
    const int h2 = lane >> 4;
    const int h  = wid * 2 + h2;
    const int pt = lane & 15;
    const int cr = (lane >> 2) & 3;
    const int e  = lane & 3;

    // softmax over this head's 16 logits
    const float lg = qout[q * 384 + 256 + h * 16 + pt];
    float m = lg;
#pragma unroll
    for (int s = 8; s > 0; s >>= 1)
        m = fmaxf(m, __shfl_xor_sync(0xffffffffu, m, s));
    const float eo = __expf(lg - m);
    float ssum = eo;
#pragma unroll
    for (int s = 8; s > 0; s >>= 1)
        ssum += __shfl_xor_sync(0xffffffffu, ssum, s);
    const float aw = eo / ssum;

    // geometry: all 32 lanes (2 heads x 16 points)
    {
        const int l = pt >> 2;
        const int p = pt & 3;
        const int W = WW[l];
        const float2 rxy = *(const float2*)&rp[(q * 4 + l) * 2];
        const int oj = q * 384 + (((h * 4 + l) * 4) + p) * 2;
        const float2 oxy = *(const float2*)&qout[oj];
        const float x = fmaf(rxy.x, (float)W, oxy.x) - 0.5f;
        const float y = fmaf(rxy.y, (float)W, oxy.y) - 0.5f;
        const float xf = floorf(x), yf = floorf(y);
        const float dx = x - xf, dy = y - yf;
        const int xc = min(max((int)xf, -2), W);
        const int yc = min(max((int)yf, -2), W);
        const int B0 = (PB[l] + (yc + 2) * (W + 4) + (xc + 2)) * 64;   // 64B/pixel
        const float wx1 = aw * dx;
        const float wx0 = aw - wx1;
#pragma unroll
        for (int c = 0; c < 4; c++) {
            const int cxx = c & 1, cyy = c >> 1;
            const int off = B0 + (cyy * (W + 4) + cxx) * 64;
            const float w = (cxx ? wx1 : wx0) * (cyy ? dy : (1.f - dy));
            swo[qi][h][pt][c] = make_uint2(__float_as_uint(w), (uint32_t)off);
        }
    }
    __syncwarp();

    // gather: one LDG.128 per point per lane (16B of a corner pixel)
    const char* __restrict__ vb = (const char*)value + (size_t)h * PADROWS * 64 + e * 16;
    const uint2* __restrict__ sp = &swo[qi][h][0][cr];
    float acc[8];
#pragma unroll
    for (int j = 0; j < 8; j++) acc[j] = 0.f;

#pragma unroll
    for (int i = 0; i < 16; i++) {
        const uint2 wo = sp[i * 4];
        const float w = __uint_as_float(wo.x);
        const uint4 raw = *(const uint4*)(vb + wo.y);
        const __half2* hp = (const __half2*)&raw;
#pragma unroll
        for (int j = 0; j < 4; j++) {
            const float2 f = __half22float2(hp[j]);
            acc[2 * j + 0] = fmaf(w, f.x, acc[2 * j + 0]);
            acc[2 * j + 1] = fmaf(w, f.y, acc[2 * j + 1]);
        }
    }

    // reduce over corner groups
#pragma unroll
    for (int s = 4; s <= 8; s <<= 1)
#pragma unroll
        for (int j = 0; j < 8; j++)
            acc[j] += __shfl_xor_sync(0xffffffffu, acc[j], s);

    if (cr == 0) {
        uint4 hv;
        uint32_t* hw = (uint32_t*)&hv;
#pragma unroll
        for (int j = 0; j < 4; j++)
            hw[j] = packh2(acc[2 * j], acc[2 * j + 1]);
        const size_t o = (size_t)q * 256 + h * 32 + e * 8;
        *(uint4*)&accb[o] = hv;
    }
}

// ---------------------------------------------------------------------------
// Launch
// ---------------------------------------------------------------------------
extern "C" void kernel_launch(void* const* d_in, const int* in_sizes, int n_in,
                              void* d_out, int out_size)
{
    const float* query    = (const float*)d_in[0];
    const float* value_in = (const float*)d_in[1];
    const float* rp       = (const float*)d_in[2];
    const float* Wv       = (const float*)d_in[3];
    const float* bv       = (const float*)d_in[4];
    const float* Ws       = (const float*)d_in[5];
    const float* bs       = (const float*)d_in[6];
    const float* Wa       = (const float*)d_in[7];
    const float* ba       = (const float*)d_in[8];
    const float* Wo       = (const float*)d_in[9];
    const float* bo       = (const float*)d_in[10];
    float* out = (float*)d_out;

    __half *pvh, *pac, *pwv, *pwq, *pwo;
    float *pq, *pbq;
    cudaGetSymbolAddress((void**)&pvh, g_value_h);
    cudaGetSymbolAddress((void**)&pq,  g_qout);
    cudaGetSymbolAddress((void**)&pac, g_acc);
    cudaGetSymbolAddress((void**)&pbq, g_bq);
    cudaGetSymbolAddress((void**)&pwv, g_Wv);
    cudaGetSymbolAddress((void**)&pwq, g_Wq);
    cudaGetSymbolAddress((void**)&pwo, g_Wo);

    const int SMEM = 81920;   // 16K A + 64K B -> 2 CTAs/SM
    cudaFuncSetAttribute(proj_fused, cudaFuncAttributeMaxDynamicSharedMemorySize, SMEM);
    cudaFuncSetAttribute(gemm_out,   cudaFuncAttributeMaxDynamicSharedMemorySize, SMEM);

    const int M = LQ;
    const int GBY = (M + 127) / 128;  // 337
    dim3 blk(256);

    // Combined prep (zero pads + weights + bias), single launch
    prep_all<<<(ZPN + 229760 + 255) / 256, 256>>>(Wv, Ws, Wa, Wo, bs, ba,
                                                  pvh, pwv, pwq, pwo, pbq);

    // Fused value + offsets/logits projections (one launch)
    proj_fused<<<dim3(5, GBY), blk, SMEM>>>(
        value_in, query, pwv, pwq, bv, pbq, pvh, pq, M);

    // Deformable sampling: 2 queries/block, 2 heads/warp, head-major value
    msda_sample<<<LQ / 2, 256>>>(pvh, pq, rp, pac);

    // Output projection
    gemm_out<<<dim3(2, GBY), blk, SMEM>>>(pac, pwo, bo, out, M);
}